// round 7
// baseline (speedup 1.0000x reference)
#include <cuda_runtime.h>
#include <cuda_fp16.h>
#include <math.h>
#include <cstdint>

// Problem constants
#define Bsz 2
#define Lsz 4096
#define Dsz 1024
#define Hsz 16
#define DKs 64
#define TOK (Bsz*Lsz)          // 8192
#define BH  (Bsz*Hsz)          // 32
#define NCHUNK 16
#define KD 1024                // GEMM K
#define NQKV 3072

// ---------------- scratch ---------------------------------------------------
__device__ float g_qkv [TOK*NQKV];     // fused q|k|v raw projections
__device__ float g_praw[TOK*64];
__device__ float g_qn  [TOK*Dsz];
__device__ float g_kb  [TOK*Dsz];
__device__ float g_vs  [TOK*Dsz];
__device__ float g_lgf [BH*Lsz];
__device__ float g_lgs [BH*Lsz];
__device__ float g_wf  [BH*Lsz];
__device__ float g_ws  [BH*Lsz];
__device__ float g_alpha[BH*Lsz];
__device__ float g_dinv[2*BH];
__device__ float g_Mpart[NCHUNK*2*BH*DKs*DKs];
__device__ float g_M   [2*BH*DKs*DKs];
// fp16 operands: activations single, weights hi/lo split
__device__ __half g_xh[TOK*Dsz];
__device__ __half g_oh[TOK*Dsz];
__device__ __half g_wqkvh[NQKV*Dsz], g_wqkvl[NQKV*Dsz];
__device__ __half g_woh[Dsz*Dsz], g_wol[Dsz*Dsz];
__device__ __half g_wgh[64*Dsz],  g_wgl[64*Dsz];

// ---------------- f32x2 helpers ---------------------------------------------
__device__ __forceinline__ unsigned long long pk2(float lo, float hi) {
    unsigned long long r;
    asm("mov.b64 %0, {%1, %2};" : "=l"(r) : "r"(__float_as_uint(lo)), "r"(__float_as_uint(hi)));
    return r;
}
__device__ __forceinline__ unsigned long long pkdup(float a) {
    unsigned long long r; unsigned int ai = __float_as_uint(a);
    asm("mov.b64 %0, {%1, %1};" : "=l"(r) : "r"(ai));
    return r;
}
__device__ __forceinline__ void fma2(unsigned long long& d, unsigned long long a, unsigned long long b) {
    asm("fma.rn.f32x2 %0, %1, %2, %0;" : "+l"(d) : "l"(a), "l"(b));
}
__device__ __forceinline__ unsigned long long mul2(unsigned long long a, unsigned long long b) {
    unsigned long long d;
    asm("mul.rn.f32x2 %0, %1, %2;" : "=l"(d) : "l"(a), "l"(b));
    return d;
}
__device__ __forceinline__ float2 upk2(unsigned long long v) {
    unsigned int lo, hi;
    asm("mov.b64 {%0, %1}, %2;" : "=r"(lo), "=r"(hi) : "l"(v));
    return make_float2(__uint_as_float(lo), __uint_as_float(hi));
}
__device__ __forceinline__ float sigmoidf_(float x) { return 1.0f / (1.0f + expf(-x)); }

// ---------------- mma.sync helpers ------------------------------------------
__device__ __forceinline__ uint32_t s2u32(const void* p) {
    uint32_t a;
    asm("{ .reg .u64 t; cvta.to.shared.u64 t, %1; cvt.u32.u64 %0, t; }" : "=r"(a) : "l"(p));
    return a;
}
__device__ __forceinline__ void cpa16(uint32_t s, const void* g) {
    asm volatile("cp.async.cg.shared.global [%0], [%1], 16;" :: "r"(s), "l"(g));
}
__device__ __forceinline__ void cpa_commit() { asm volatile("cp.async.commit_group;" ::: "memory"); }
template<int N> __device__ __forceinline__ void cpa_wait() { asm volatile("cp.async.wait_group %0;" :: "n"(N) : "memory"); }

__device__ __forceinline__ void ldm4(uint32_t* r, uint32_t addr) {
    asm volatile("ldmatrix.sync.aligned.m8n8.x4.shared.b16 {%0,%1,%2,%3}, [%4];"
        : "=r"(r[0]), "=r"(r[1]), "=r"(r[2]), "=r"(r[3]) : "r"(addr));
}
__device__ __forceinline__ void mma_f16(float* d, const uint32_t* a, const uint32_t* b) {
    asm volatile(
        "mma.sync.aligned.m16n8k16.row.col.f32.f16.f16.f32 "
        "{%0,%1,%2,%3}, {%4,%5,%6,%7}, {%8,%9}, {%0,%1,%2,%3};"
        : "+f"(d[0]), "+f"(d[1]), "+f"(d[2]), "+f"(d[3])
        : "r"(a[0]), "r"(a[1]), "r"(a[2]), "r"(a[3]), "r"(b[0]), "r"(b[1]));
}
// f16-accumulate variant (potentially 2x rate): D/C are 2 x f16x2 regs
__device__ __forceinline__ void mma_f16acc(uint32_t* d, const uint32_t* a, const uint32_t* b) {
    asm volatile(
        "mma.sync.aligned.m16n8k16.row.col.f16.f16.f16.f16 "
        "{%0,%1}, {%2,%3,%4,%5}, {%6,%7}, {%0,%1};"
        : "+r"(d[0]), "+r"(d[1])
        : "r"(a[0]), "r"(a[1]), "r"(a[2]), "r"(a[3]), "r"(b[0]), "r"(b[1]));
}

// ---------------- big GEMM: C = A @ (Bh+Bl)^T, A fp16, f32 acc --------------
// hi term: f32-acc mma; lo term: f16-acc mma (values tiny), merged at epilogue.
// 512 threads, CTA 128x128, warp tile 32x32, 4-stage cp.async pipeline.
// smem rows padded to 80B (5 x 16B chunks) -> conflict-free ldmatrix.
__global__ __launch_bounds__(512, 1) void gemm_f16_512(
    const __half* __restrict__ A,
    const __half* __restrict__ Bhw, const __half* __restrict__ Blw,
    float* __restrict__ C, int ldC)
{
    constexpr int UNITS = 128 * 5;            // 16B units per tile
    constexpr int STAGE_U = 3 * UNITS;        // A | Bh | Bl
    constexpr int NSTAGE_K = KD / 32;         // 32

    extern __shared__ __align__(16) unsigned char smem[];
    const uint32_t sbase = s2u32(smem);
    const int tid = threadIdx.x;
    const int wid = tid >> 5;
    const int lane = tid & 31;
    const int warp_m = wid >> 2;              // 0..3
    const int warp_n = wid & 3;               // 0..3
    const int rowA0 = blockIdx.y * 128;
    const int rowB0 = blockIdx.x * 128;

    float acc[2][4][4];
    uint32_t accl[2][4][2];
#pragma unroll
    for (int mt = 0; mt < 2; mt++)
#pragma unroll
        for (int nt = 0; nt < 4; nt++) {
#pragma unroll
            for (int j = 0; j < 4; j++) acc[mt][nt][j] = 0.0f;
            accl[mt][nt][0] = 0u; accl[mt][nt][1] = 0u;
        }

    auto load_stage = [&](int stage, int kc) {
        uint32_t base = sbase + stage * STAGE_U * 16;
        const int col = kc * 32;
        int r = tid >> 2, c = tid & 3;
        uint32_t dst = base + (uint32_t)(r * 5 + c) * 16;
        cpa16(dst, A + (size_t)(rowA0 + r) * KD + col + c * 8);
        cpa16(dst + UNITS * 16,     Bhw + (size_t)(rowB0 + r) * KD + col + c * 8);
        cpa16(dst + 2 * UNITS * 16, Blw + (size_t)(rowB0 + r) * KD + col + c * 8);
    };

    const int aRow = lane & 15;
    const int aHalf = (lane >> 4) & 1;
    const int bRow = (lane & 7) + ((lane >> 4) << 3);
    const int bHalf = (lane >> 3) & 1;

    load_stage(0, 0); cpa_commit();
    load_stage(1, 1); cpa_commit();
    load_stage(2, 2); cpa_commit();

#pragma unroll 1
    for (int kc = 0; kc < NSTAGE_K; kc++) {
        cpa_wait<2>();
        __syncthreads();
        if (kc + 3 < NSTAGE_K) load_stage((kc + 3) & 3, kc + 3);
        cpa_commit();

        uint32_t stg = sbase + (kc & 3) * STAGE_U * 16;
        uint32_t aB   = stg + (uint32_t)((warp_m * 32 + aRow) * 5 + aHalf) * 16;
        uint32_t bHiB = stg + (uint32_t)(UNITS + (warp_n * 32 + bRow) * 5 + bHalf) * 16;
        uint32_t bLoB = bHiB + UNITS * 16;

#pragma unroll
        for (int ks = 0; ks < 2; ks++) {
            uint32_t a[2][4], bh[8], bl[8];
#pragma unroll
            for (int mt = 0; mt < 2; mt++)
                ldm4(a[mt], aB + (uint32_t)(mt * 16 * 5 + ks * 2) * 16);
#pragma unroll
            for (int p = 0; p < 2; p++) {
                uint32_t off = (uint32_t)(p * 16 * 5 + ks * 2) * 16;
                ldm4(bh + p * 4, bHiB + off);
                ldm4(bl + p * 4, bLoB + off);
            }
#pragma unroll
            for (int mt = 0; mt < 2; mt++) {
#pragma unroll
                for (int nt = 0; nt < 4; nt++) {
                    const uint32_t* bhf = bh + (nt >> 1) * 4 + (nt & 1) * 2;
                    const uint32_t* blf = bl + (nt >> 1) * 4 + (nt & 1) * 2;
                    mma_f16(acc[mt][nt], a[mt], bhf);
                    mma_f16acc(accl[mt][nt], a[mt], blf);
                }
            }
        }
    }

    const int r0 = rowA0 + warp_m * 32 + (lane >> 2);
    const int c0 = rowB0 + warp_n * 32 + (lane & 3) * 2;
#pragma unroll
    for (int mt = 0; mt < 2; mt++) {
#pragma unroll
        for (int nt = 0; nt < 4; nt++) {
            float2 l01 = __half22float2(*(__half2*)&accl[mt][nt][0]);
            float2 l23 = __half22float2(*(__half2*)&accl[mt][nt][1]);
            float* p0 = C + (size_t)(r0 + mt * 16) * ldC + c0 + nt * 8;
            *(float2*)p0 = make_float2(acc[mt][nt][0] + l01.x, acc[mt][nt][1] + l01.y);
            *(float2*)(p0 + 8 * ldC) = make_float2(acc[mt][nt][2] + l23.x, acc[mt][nt][3] + l23.y);
        }
    }
}

// ---------------- gates GEMM: CTA 128x64, 256 threads -----------------------
__global__ __launch_bounds__(256, 1) void gemm_f16_64(
    const __half* __restrict__ A,
    const __half* __restrict__ Bhw, const __half* __restrict__ Blw,
    float* __restrict__ C, int ldC)
{
    constexpr int NT = 64;
    constexpr int AUNITS = 128 * 5;
    constexpr int BUNITS = NT * 5;
    constexpr int STAGE_U = AUNITS + 2 * BUNITS;
    constexpr int NSTAGE_K = KD / 32;

    extern __shared__ __align__(16) unsigned char smem[];
    const uint32_t sbase = s2u32(smem);
    const int tid = threadIdx.x;
    const int wid = tid >> 5;
    const int lane = tid & 31;
    const int warp_m = wid >> 1;     // 0..3, WM=32
    const int warp_n = wid & 1;      // 0..1
    const int rowA0 = blockIdx.y * 128;
    const int rowB0 = blockIdx.x * NT;

    float acc[2][4][4];
    uint32_t accl[2][4][2];
#pragma unroll
    for (int mt = 0; mt < 2; mt++)
#pragma unroll
        for (int nt = 0; nt < 4; nt++) {
#pragma unroll
            for (int j = 0; j < 4; j++) acc[mt][nt][j] = 0.0f;
            accl[mt][nt][0] = 0u; accl[mt][nt][1] = 0u;
        }

    auto load_stage = [&](int stage, int kc) {
        uint32_t base = sbase + stage * STAGE_U * 16;
        const int col = kc * 32;
#pragma unroll
        for (int i = 0; i < 2; i++) {
            int idx = tid + i * 256;
            int r = idx >> 2, c = idx & 3;
            uint32_t dst = base + (uint32_t)(r * 5 + c) * 16;
            cpa16(dst, A + (size_t)(rowA0 + r) * KD + col + c * 8);
        }
        {
            int r = tid >> 2, c = tid & 3;
            if (r < NT) {
                uint32_t dst = base + (uint32_t)(AUNITS + r * 5 + c) * 16;
                cpa16(dst, Bhw + (size_t)(rowB0 + r) * KD + col + c * 8);
                cpa16(dst + BUNITS * 16, Blw + (size_t)(rowB0 + r) * KD + col + c * 8);
            }
        }
    };

    const int aRow = lane & 15;
    const int aHalf = (lane >> 4) & 1;
    const int bRow = (lane & 7) + ((lane >> 4) << 3);
    const int bHalf = (lane >> 3) & 1;

    load_stage(0, 0); cpa_commit();
    load_stage(1, 1); cpa_commit();
    load_stage(2, 2); cpa_commit();

#pragma unroll 1
    for (int kc = 0; kc < NSTAGE_K; kc++) {
        cpa_wait<2>();
        __syncthreads();
        if (kc + 3 < NSTAGE_K) load_stage((kc + 3) & 3, kc + 3);
        cpa_commit();

        uint32_t stg = sbase + (kc & 3) * STAGE_U * 16;
        uint32_t aB   = stg + (uint32_t)((warp_m * 32 + aRow) * 5 + aHalf) * 16;
        uint32_t bHiB = stg + (uint32_t)(AUNITS + (warp_n * 32 + bRow) * 5 + bHalf) * 16;
        uint32_t bLoB = bHiB + BUNITS * 16;

#pragma unroll
        for (int ks = 0; ks < 2; ks++) {
            uint32_t a[2][4], bh[8], bl[8];
#pragma unroll
            for (int mt = 0; mt < 2; mt++)
                ldm4(a[mt], aB + (uint32_t)(mt * 16 * 5 + ks * 2) * 16);
#pragma unroll
            for (int p = 0; p < 2; p++) {
                uint32_t off = (uint32_t)(p * 16 * 5 + ks * 2) * 16;
                ldm4(bh + p * 4, bHiB + off);
                ldm4(bl + p * 4, bLoB + off);
            }
#pragma unroll
            for (int mt = 0; mt < 2; mt++) {
#pragma unroll
                for (int nt = 0; nt < 4; nt++) {
                    const uint32_t* bhf = bh + (nt >> 1) * 4 + (nt & 1) * 2;
                    const uint32_t* blf = bl + (nt >> 1) * 4 + (nt & 1) * 2;
                    mma_f16(acc[mt][nt], a[mt], bhf);
                    mma_f16acc(accl[mt][nt], a[mt], blf);
                }
            }
        }
    }

    const int r0 = rowA0 + warp_m * 32 + (lane >> 2);
    const int c0 = rowB0 + warp_n * 32 + (lane & 3) * 2;
#pragma unroll
    for (int mt = 0; mt < 2; mt++) {
#pragma unroll
        for (int nt = 0; nt < 4; nt++) {
            float2 l01 = __half22float2(*(__half2*)&accl[mt][nt][0]);
            float2 l23 = __half22float2(*(__half2*)&accl[mt][nt][1]);
            float* p0 = C + (size_t)(r0 + mt * 16) * ldC + c0 + nt * 8;
            *(float2*)p0 = make_float2(acc[mt][nt][0] + l01.x, acc[mt][nt][1] + l01.y);
            *(float2*)(p0 + 8 * ldC) = make_float2(acc[mt][nt][2] + l23.x, acc[mt][nt][3] + l23.y);
        }
    }
}

// ---------------- prep: x -> fp16 -------------------------------------------
__global__ __launch_bounds__(256) void conv_x(
    const float* __restrict__ x, __half* __restrict__ xh)
{
    int i = blockIdx.x * 256 + threadIdx.x;
    float4 v = ((const float4*)x)[i];
    __half2* o = (__half2*)(xh + i * 4);
    o[0] = __floats2half2_rn(v.x, v.y);
    o[1] = __floats2half2_rn(v.z, v.w);
}

// ---------------- prep: transpose + fp16 hi/lo split of weights -------------
__global__ __launch_bounds__(256) void split_wt(
    const float* __restrict__ W, __half* __restrict__ Bh, __half* __restrict__ Bl,
    int rowOff)
{
    __shared__ float t[32][33];
    int bx = blockIdx.x, by = blockIdx.y;
    int tx = threadIdx.x & 31, ty = threadIdx.x >> 5;
#pragma unroll
    for (int i = 0; i < 4; i++) {
        int k = by * 32 + ty + i * 8;
        t[ty + i * 8][tx] = W[(size_t)k * Dsz + bx * 32 + tx];
    }
    __syncthreads();
#pragma unroll
    for (int i = 0; i < 4; i++) {
        int n = bx * 32 + ty + i * 8 + rowOff;
        float v = t[tx][ty + i * 8];
        __half h = __float2half_rn(v);
        Bh[(size_t)n * Dsz + by * 32 + tx] = h;
        Bl[(size_t)n * Dsz + by * 32 + tx] = __float2half_rn(v - __half2float(h));
    }
}

// ---------------- prep: gate weights ----------------------------------------
__global__ __launch_bounds__(256) void split_gate(
    const float* __restrict__ Wb, const float* __restrict__ Wfd, const float* __restrict__ Wsd,
    __half* __restrict__ Gh, __half* __restrict__ Gl)
{
    int n = blockIdx.x;
    for (int k = threadIdx.x; k < Dsz; k += 256) {
        float v = 0.0f;
        if (n < 16)      v = Wb [k * Hsz + n];
        else if (n < 32) v = Wfd[k * Hsz + (n - 16)];
        else if (n < 48) v = Wsd[k * Hsz + (n - 32)];
        __half h = __float2half_rn(v);
        Gh[(size_t)n * Dsz + k] = h;
        Gl[(size_t)n * Dsz + k] = __float2half_rn(v - __half2float(h));
    }
}

// ---------------- per-(token,head) transform --------------------------------
__global__ __launch_bounds__(256) void transform_k(
    const float* __restrict__ qkv, const float* __restrict__ praw,
    const float* __restrict__ bfd, const float* __restrict__ bsd,
    const float* __restrict__ Wtf1, const float* __restrict__ btf1,
    const float* __restrict__ Wtf2, const float* __restrict__ btf2,
    float* __restrict__ qn, float* __restrict__ kb, float* __restrict__ vsc,
    float* __restrict__ lgF, float* __restrict__ lgS, float* __restrict__ alp)
{
    __shared__ float sW1[64 * 32];
    __shared__ float sb1[32];
    __shared__ float sW2[32];
    const int tid = threadIdx.x;
    for (int i = tid; i < 2048; i += 256) sW1[i] = Wtf1[i];
    if (tid < 32) { sb1[tid] = btf1[tid]; sW2[tid] = Wtf2[tid]; }
    __syncthreads();

    const int lane = tid & 31;
    const int gw = blockIdx.x * 8 + (tid >> 5);
    const int head = gw & 15;
    const int tok  = gw >> 4;
    const int b = tok >> 12;
    const int l = tok & (Lsz - 1);
    const int bh = b * Hsz + head;
    const unsigned FULL = 0xffffffffu;

    const float* qr = qkv + (size_t)tok * NQKV + head * DKs;
    float q0 = qr[lane], q1 = qr[lane + 32];
    float ss = q0*q0 + q1*q1;
#pragma unroll
    for (int o = 16; o; o >>= 1) ss += __shfl_xor_sync(FULL, ss, o);
    float inv = 1.0f / fmaxf(sqrtf(ss), 1e-12f);
    size_t obase = ((size_t)bh * Lsz + l) * DKs;
    qn[obase + lane]      = q0 * inv;
    qn[obase + lane + 32] = q1 * inv;

    const float* kr = qr + 1024;
    float k0 = kr[lane], k1 = kr[lane + 32];
    float ks = k0*k0 + k1*k1;
#pragma unroll
    for (int o = 16; o; o >>= 1) ks += __shfl_xor_sync(FULL, ks, o);
    float kinv = 1.0f / fmaxf(sqrtf(ks), 1e-12f);
    float beta = sigmoidf_(praw[(size_t)tok * 64 + head]);
    float kb0 = k0 * kinv * beta;
    float kb1 = k1 * kinv * beta;
    kb[obase + lane]      = kb0;
    kb[obase + lane + 32] = kb1;

    const float* vr = qr + 2048;
    vsc[obase + lane]      = vr[lane]      * beta;
    vsc[obase + lane + 32] = vr[lane + 32] * beta;

    if (lane == 0) {
        float fdl = praw[(size_t)tok * 64 + 16 + head] + bfd[head];
        float sdl = praw[(size_t)tok * 64 + 32 + head] + bsd[head];
        lgF[(size_t)bh * Lsz + l] = logf(sigmoidf_(fdl) + 1e-6f);
        lgS[(size_t)bh * Lsz + l] = logf(sigmoidf_(sdl) + 1e-6f);
    }

    float acc = 0.0f;
#pragma unroll
    for (int i = 0; i < 64; i++) {
        float kbi = __shfl_sync(FULL, (i < 32) ? kb0 : kb1, i & 31);
        acc += kbi * sW1[i * 32 + lane];
    }
    float hmid = acc + sb1[lane];
    hmid = hmid * (1.0f / (1.0f + expf(-hmid)));
    float t = hmid * sW2[lane];
#pragma unroll
    for (int o = 16; o; o >>= 1) t += __shfl_xor_sync(FULL, t, o);
    if (lane == 0) {
        float tf = sigmoidf_(t + btf2[0]);
        tf = fminf(fmaxf(tf, 0.01f), 0.99f);
        alp[(size_t)bh * Lsz + l] = 0.5f + 0.3f * tf;
    }
}

// ---------------- fp64 scan per (b,h) ---------------------------------------
__global__ __launch_bounds__(512) void scan_k(
    const float* __restrict__ lgF, const float* __restrict__ lgS,
    float* __restrict__ wF, float* __restrict__ wS, float* __restrict__ dinv)
{
    __shared__ double sm[512];
    const int bh = blockIdx.x;
    const int tid = threadIdx.x;
    for (int s = 0; s < 2; s++) {
        const float* lg = s ? lgS : lgF;
        float* w = s ? wS : wF;
        size_t base = (size_t)bh * Lsz + tid * 8;
        double loc[8];
        double run = 0.0;
#pragma unroll
        for (int j = 0; j < 8; j++) { run += (double)lg[base + j]; loc[j] = run; }
        sm[tid] = run;
        __syncthreads();
        for (int off = 1; off < 512; off <<= 1) {
            double v = (tid >= off) ? sm[tid - off] : 0.0;
            __syncthreads();
            sm[tid] += v;
            __syncthreads();
        }
        double total = sm[511];
        double excl = sm[tid] - run;
        double wsum = 0.0;
#pragma unroll
        for (int j = 0; j < 8; j++) {
            double wv = exp(total - (excl + loc[j]));
            w[base + j] = (float)wv;
            wsum += wv;
        }
        __syncthreads();
        sm[tid] = wsum;
        __syncthreads();
        for (int off = 256; off; off >>= 1) {
            if (tid < off) sm[tid] += sm[tid + off];
            __syncthreads();
        }
        if (tid == 0) dinv[s * BH + bh] = (float)(1.0 / (sm[0] + 1e-6));
        __syncthreads();
    }
}

// ---------------- state partials --------------------------------------------
__global__ __launch_bounds__(256) void state_partial(
    const float* __restrict__ kb, const float* __restrict__ vsc,
    const float* __restrict__ wF, const float* __restrict__ wS,
    float* __restrict__ Mpart)
{
    __shared__ __align__(16) float skb[32][68];
    __shared__ __align__(16) float svs[32][68];
    __shared__ float swf[32], sws[32];
    const int bh = blockIdx.x, ch = blockIdx.y;
    const int tid = threadIdx.x;
    const int tx = tid & 15, ty = tid >> 4;
    const int lr = tid >> 3, lc0 = (tid & 7) * 8;
    const int LPC = Lsz / NCHUNK;

    unsigned long long acc[4][4];
#pragma unroll
    for (int r = 0; r < 4; r++)
#pragma unroll
        for (int c = 0; c < 4; c++) acc[r][c] = 0ULL;

    const float* kp = kb  + ((size_t)bh * Lsz + ch * LPC) * DKs;
    const float* vp = vsc + ((size_t)bh * Lsz + ch * LPC) * DKs;
    const float* wfp = wF + (size_t)bh * Lsz + ch * LPC;
    const float* wsp = wS + (size_t)bh * Lsz + ch * LPC;

    for (int l0 = 0; l0 < LPC; l0 += 32) {
        *(float4*)&skb[lr][lc0]     = *(const float4*)(kp + (size_t)(l0 + lr) * DKs + lc0);
        *(float4*)&skb[lr][lc0 + 4] = *(const float4*)(kp + (size_t)(l0 + lr) * DKs + lc0 + 4);
        *(float4*)&svs[lr][lc0]     = *(const float4*)(vp + (size_t)(l0 + lr) * DKs + lc0);
        *(float4*)&svs[lr][lc0 + 4] = *(const float4*)(vp + (size_t)(l0 + lr) * DKs + lc0 + 4);
        if (tid < 32) swf[tid] = wfp[l0 + tid];
        else if (tid < 64) sws[tid - 32] = wsp[l0 + tid - 32];
        __syncthreads();
#pragma unroll
        for (int l = 0; l < 32; l++) {
            unsigned long long wpair = pk2(swf[l], sws[l]);
            unsigned long long kw[4], vd[4];
#pragma unroll
            for (int r = 0; r < 4; r++) kw[r] = mul2(pkdup(skb[l][ty*4 + r]), wpair);
#pragma unroll
            for (int c = 0; c < 4; c++) vd[c] = pkdup(svs[l][tx*4 + c]);
#pragma unroll
            for (int r = 0; r < 4; r++)
#pragma unroll
                for (int c = 0; c < 4; c++) fma2(acc[r][c], kw[r], vd[c]);
        }
        __syncthreads();
    }
    size_t base = (size_t)ch * (2 * BH * 4096) + (size_t)bh * 4096;
#pragma unroll
    for (int r = 0; r < 4; r++)
#pragma unroll
        for (int c = 0; c < 4; c++) {
            float2 fs = upk2(acc[r][c]);
            int de = (ty*4 + r) * 64 + (tx*4 + c);
            Mpart[base + de] = fs.x;
            Mpart[base + BH * 4096 + de] = fs.y;
        }
}

__global__ __launch_bounds__(256) void reduceM(
    const float* __restrict__ Mpart, const float* __restrict__ dinv, float* __restrict__ M)
{
    int idx = blockIdx.x * 256 + threadIdx.x;
    if (idx >= 2 * BH * 4096) return;
    float s = 0.0f;
#pragma unroll
    for (int c = 0; c < NCHUNK; c++) s += Mpart[(size_t)c * (2 * BH * 4096) + idx];
    M[idx] = s * dinv[idx >> 12];
}

// ---------------- readout -> fp16 o for final GEMM --------------------------
__global__ __launch_bounds__(256) void readout_k(
    const float* __restrict__ qn, const float* __restrict__ M,
    const float* __restrict__ alp,
    __half* __restrict__ oh)
{
    __shared__ unsigned long long sMp[64 * 64];
    const int bh = blockIdx.x;
    const int tid = threadIdx.x;
    const float* Mf = M + (size_t)bh * 4096;
    const float* Ms = M + (size_t)(BH + bh) * 4096;
    for (int p = tid; p < 4096; p += 256) sMp[p] = pk2(Mf[p], Ms[p]);
    __syncthreads();

    const int l = blockIdx.y * 256 + tid;
    const float* qp = qn + ((size_t)bh * Lsz + l) * DKs;
    float a = alp[(size_t)bh * Lsz + l];
    int b = bh >> 4, h = bh & 15;
    size_t ob = ((size_t)(b * Lsz + l)) * Dsz + h * DKs;

#pragma unroll
    for (int e0 = 0; e0 < 64; e0 += 16) {
        unsigned long long acc[16];
#pragma unroll
        for (int j = 0; j < 16; j++) acc[j] = 0ULL;
        for (int d0 = 0; d0 < 64; d0 += 4) {
            float4 qv = *(const float4*)(qp + d0);
            unsigned long long qd[4];
            qd[0] = pkdup(qv.x); qd[1] = pkdup(qv.y); qd[2] = pkdup(qv.z); qd[3] = pkdup(qv.w);
#pragma unroll
            for (int dd = 0; dd < 4; dd++) {
#pragma unroll
                for (int j = 0; j < 16; j++)
                    fma2(acc[j], qd[dd], sMp[(d0 + dd) * 64 + e0 + j]);
            }
        }
#pragma unroll
        for (int j = 0; j < 16; j++) {
            float2 fs = upk2(acc[j]);
            float val = a * fs.x + (1.0f - a) * fs.y;
            oh[ob + e0 + j] = __float2half_rn(val);
        }
    }
}

// ---------------- launch ----------------------------------------------------
extern "C" void kernel_launch(void* const* d_in, const int* in_sizes, int n_in,
                              void* d_out, int out_size)
{
    const float* x    = (const float*)d_in[0];
    const float* Wq   = (const float*)d_in[1];
    const float* Wk   = (const float*)d_in[2];
    const float* Wv   = (const float*)d_in[3];
    const float* Wb   = (const float*)d_in[4];
    const float* Wo   = (const float*)d_in[5];
    const float* Wfd  = (const float*)d_in[6];
    const float* bfd  = (const float*)d_in[7];
    const float* Wsd  = (const float*)d_in[8];
    const float* bsd  = (const float*)d_in[9];
    const float* Wtf1 = (const float*)d_in[10];
    const float* btf1 = (const float*)d_in[11];
    const float* Wtf2 = (const float*)d_in[12];
    const float* btf2 = (const float*)d_in[13];

    float *qkv, *praw, *qn, *kb, *vs, *lgf, *lgs, *wf, *ws, *alpha, *dinv, *Mpart, *M;
    __half *xh, *oh, *wqkvh, *wqkvl, *woh, *wol, *wgh, *wgl;
    cudaGetSymbolAddress((void**)&qkv,  g_qkv);
    cudaGetSymbolAddress((void**)&praw, g_praw);
    cudaGetSymbolAddress((void**)&qn,   g_qn);
    cudaGetSymbolAddress((void**)&kb,   g_kb);
    cudaGetSymbolAddress((void**)&vs,   g_vs);
    cudaGetSymbolAddress((void**)&lgf,  g_lgf);
    cudaGetSymbolAddress((void**)&lgs,  g_lgs);
    cudaGetSymbolAddress((void**)&wf,   g_wf);
    cudaGetSymbolAddress((void**)&ws,   g_ws);
    cudaGetSymbolAddress((void**)&alpha,g_alpha);
    cudaGetSymbolAddress((void**)&dinv, g_dinv);
    cudaGetSymbolAddress((void**)&Mpart,g_Mpart);
    cudaGetSymbolAddress((void**)&M,    g_M);
    cudaGetSymbolAddress((void**)&xh,   g_xh);
    cudaGetSymbolAddress((void**)&oh,   g_oh);
    cudaGetSymbolAddress((void**)&wqkvh,g_wqkvh);
    cudaGetSymbolAddress((void**)&wqkvl,g_wqkvl);
    cudaGetSymbolAddress((void**)&woh,  g_woh);
    cudaGetSymbolAddress((void**)&wol,  g_wol);
    cudaGetSymbolAddress((void**)&wgh,  g_wgh);
    cudaGetSymbolAddress((void**)&wgl,  g_wgl);

    const int SM512 = 4 * (3 * 128 * 5) * 16;                 // 122880
    const int SM64  = 4 * (128 * 5 + 2 * 64 * 5) * 16;        // 81920
    cudaFuncSetAttribute(gemm_f16_512, cudaFuncAttributeMaxDynamicSharedMemorySize, SM512);
    cudaFuncSetAttribute(gemm_f16_64,  cudaFuncAttributeMaxDynamicSharedMemorySize, SM64);

    // prep: exactly 4 launches so QKV GEMM is launch #5 (ncu capture slot)
    conv_x<<<TOK * Dsz / 4 / 256, 256>>>(x, xh);
    dim3 gW(32, 32);
    split_wt<<<gW, 256>>>(Wq, wqkvh, wqkvl, 0);
    split_wt<<<gW, 256>>>(Wk, wqkvh, wqkvl, 1024);
    split_wt<<<gW, 256>>>(Wv, wqkvh, wqkvl, 2048);

    // fused QKV projection — launch #5, captured by ncu
    gemm_f16_512<<<dim3(NQKV / 128, TOK / 128), 512, SM512>>>(xh, wqkvh, wqkvl, qkv, NQKV);

    split_wt<<<gW, 256>>>(Wo, woh, wol, 0);
    split_gate<<<64, 256>>>(Wb, Wfd, Wsd, wgh, wgl);
    gemm_f16_64<<<dim3(1, TOK / 128), 256, SM64>>>(xh, wgh, wgl, praw, 64);

    transform_k<<<TOK * Hsz / 8, 256>>>(qkv, praw, bfd, bsd,
                                        Wtf1, btf1, Wtf2, btf2,
                                        qn, kb, vs, lgf, lgs, alpha);
    scan_k<<<BH, 512>>>(lgf, lgs, wf, ws, dinv);
    state_partial<<<dim3(BH, NCHUNK), 256>>>(kb, vs, wf, ws, Mpart);
    reduceM<<<(2 * BH * 4096 + 255) / 256, 256>>>(Mpart, dinv, M);
    readout_k<<<dim3(BH, Lsz / 256), 256>>>(qn, M, alpha, oh);

    gemm_f16_512<<<dim3(Dsz / 128, TOK / 128), 512, SM512>>>(oh, woh, wol, (float*)d_out, Dsz);
}

// round 8
// speedup vs baseline: 1.2271x; 1.2271x over previous
#include <cuda_runtime.h>
#include <cuda_fp16.h>
#include <math.h>
#include <cstdint>

// Problem constants
#define Bsz 2
#define Lsz 4096
#define Dsz 1024
#define Hsz 16
#define DKs 64
#define TOK (Bsz*Lsz)          // 8192
#define BH  (Bsz*Hsz)          // 32
#define NCHUNK 16
#define KD 1024                // GEMM K
#define NQKV 3072

// ---------------- scratch ---------------------------------------------------
__device__ float g_qkv [TOK*NQKV];     // fused q|k|v raw projections
__device__ float g_praw[TOK*64];
__device__ float g_kb  [TOK*Dsz];
__device__ float g_vs  [TOK*Dsz];
__device__ float g_lgf [BH*Lsz];
__device__ float g_lgs [BH*Lsz];
__device__ float g_wf  [BH*Lsz];
__device__ float g_ws  [BH*Lsz];
__device__ float g_alpha[BH*Lsz];
__device__ float g_dinv[2*BH];
__device__ float g_Mpart[NCHUNK*2*BH*DKs*DKs];
// fp16 operands
__device__ __half g_xh[TOK*Dsz];
__device__ __half g_oh[TOK*Dsz];
__device__ __half g_qh[TOK*Dsz];       // q normalized, [bh][l][64]
__device__ __half g_Mt[BH*128*DKs];    // M transposed: [bh][e'(0..127)][d], e'<64 fast
__device__ __half g_wqkvh[NQKV*Dsz], g_wqkvl[NQKV*Dsz];
__device__ __half g_woh[Dsz*Dsz], g_wol[Dsz*Dsz];
__device__ __half g_wgh[64*Dsz],  g_wgl[64*Dsz];

// ---------------- f32x2 helpers ---------------------------------------------
__device__ __forceinline__ unsigned long long pk2(float lo, float hi) {
    unsigned long long r;
    asm("mov.b64 %0, {%1, %2};" : "=l"(r) : "r"(__float_as_uint(lo)), "r"(__float_as_uint(hi)));
    return r;
}
__device__ __forceinline__ unsigned long long pkdup(float a) {
    unsigned long long r; unsigned int ai = __float_as_uint(a);
    asm("mov.b64 %0, {%1, %1};" : "=l"(r) : "r"(ai));
    return r;
}
__device__ __forceinline__ void fma2(unsigned long long& d, unsigned long long a, unsigned long long b) {
    asm("fma.rn.f32x2 %0, %1, %2, %0;" : "+l"(d) : "l"(a), "l"(b));
}
__device__ __forceinline__ unsigned long long mul2(unsigned long long a, unsigned long long b) {
    unsigned long long d;
    asm("mul.rn.f32x2 %0, %1, %2;" : "=l"(d) : "l"(a), "l"(b));
    return d;
}
__device__ __forceinline__ float2 upk2(unsigned long long v) {
    unsigned int lo, hi;
    asm("mov.b64 {%0, %1}, %2;" : "=r"(lo), "=r"(hi) : "l"(v));
    return make_float2(__uint_as_float(lo), __uint_as_float(hi));
}
__device__ __forceinline__ float sigmoidf_(float x) { return 1.0f / (1.0f + expf(-x)); }

// ---------------- mma.sync helpers ------------------------------------------
__device__ __forceinline__ uint32_t s2u32(const void* p) {
    uint32_t a;
    asm("{ .reg .u64 t; cvta.to.shared.u64 t, %1; cvt.u32.u64 %0, t; }" : "=r"(a) : "l"(p));
    return a;
}
__device__ __forceinline__ void cpa16(uint32_t s, const void* g) {
    asm volatile("cp.async.cg.shared.global [%0], [%1], 16;" :: "r"(s), "l"(g));
}
__device__ __forceinline__ void cpa_commit() { asm volatile("cp.async.commit_group;" ::: "memory"); }
template<int N> __device__ __forceinline__ void cpa_wait() { asm volatile("cp.async.wait_group %0;" :: "n"(N) : "memory"); }

__device__ __forceinline__ void ldm4(uint32_t* r, uint32_t addr) {
    asm volatile("ldmatrix.sync.aligned.m8n8.x4.shared.b16 {%0,%1,%2,%3}, [%4];"
        : "=r"(r[0]), "=r"(r[1]), "=r"(r[2]), "=r"(r[3]) : "r"(addr));
}
__device__ __forceinline__ void mma_f16(float* d, const uint32_t* a, const uint32_t* b) {
    asm volatile(
        "mma.sync.aligned.m16n8k16.row.col.f32.f16.f16.f32 "
        "{%0,%1,%2,%3}, {%4,%5,%6,%7}, {%8,%9}, {%0,%1,%2,%3};"
        : "+f"(d[0]), "+f"(d[1]), "+f"(d[2]), "+f"(d[3])
        : "r"(a[0]), "r"(a[1]), "r"(a[2]), "r"(a[3]), "r"(b[0]), "r"(b[1]));
}

// ---------------- big GEMM: C = A @ (Bh+Bl)^T, A fp16, 2-term, f32 acc ------
// 512 threads, CTA 128x128, warp tile 32x32, 4-stage cp.async pipeline.
// smem rows padded to 80B (5 x 16B chunks) -> conflict-free ldmatrix.
__global__ __launch_bounds__(512, 1) void gemm_f16_512(
    const __half* __restrict__ A,
    const __half* __restrict__ Bhw, const __half* __restrict__ Blw,
    float* __restrict__ C, int ldC)
{
    constexpr int UNITS = 128 * 5;            // 16B units per tile
    constexpr int STAGE_U = 3 * UNITS;        // A | Bh | Bl
    constexpr int NSTAGE_K = KD / 32;         // 32

    extern __shared__ __align__(16) unsigned char smem[];
    const uint32_t sbase = s2u32(smem);
    const int tid = threadIdx.x;
    const int wid = tid >> 5;
    const int lane = tid & 31;
    const int warp_m = wid >> 2;              // 0..3
    const int warp_n = wid & 3;               // 0..3
    const int rowA0 = blockIdx.y * 128;
    const int rowB0 = blockIdx.x * 128;

    float acc[2][4][4];
#pragma unroll
    for (int mt = 0; mt < 2; mt++)
#pragma unroll
        for (int nt = 0; nt < 4; nt++)
#pragma unroll
            for (int j = 0; j < 4; j++) acc[mt][nt][j] = 0.0f;

    auto load_stage = [&](int stage, int kc) {
        uint32_t base = sbase + stage * STAGE_U * 16;
        const int col = kc * 32;
        int r = tid >> 2, c = tid & 3;
        uint32_t dst = base + (uint32_t)(r * 5 + c) * 16;
        cpa16(dst, A + (size_t)(rowA0 + r) * KD + col + c * 8);
        cpa16(dst + UNITS * 16,     Bhw + (size_t)(rowB0 + r) * KD + col + c * 8);
        cpa16(dst + 2 * UNITS * 16, Blw + (size_t)(rowB0 + r) * KD + col + c * 8);
    };

    const int aRow = lane & 15;
    const int aHalf = (lane >> 4) & 1;
    const int bRow = (lane & 7) + ((lane >> 4) << 3);
    const int bHalf = (lane >> 3) & 1;

    load_stage(0, 0); cpa_commit();
    load_stage(1, 1); cpa_commit();
    load_stage(2, 2); cpa_commit();

#pragma unroll 1
    for (int kc = 0; kc < NSTAGE_K; kc++) {
        cpa_wait<2>();
        __syncthreads();
        if (kc + 3 < NSTAGE_K) load_stage((kc + 3) & 3, kc + 3);
        cpa_commit();

        uint32_t stg = sbase + (kc & 3) * STAGE_U * 16;
        uint32_t aB   = stg + (uint32_t)((warp_m * 32 + aRow) * 5 + aHalf) * 16;
        uint32_t bHiB = stg + (uint32_t)(UNITS + (warp_n * 32 + bRow) * 5 + bHalf) * 16;
        uint32_t bLoB = bHiB + UNITS * 16;

#pragma unroll
        for (int ks = 0; ks < 2; ks++) {
            uint32_t a[2][4], bh[8], bl[8];
#pragma unroll
            for (int mt = 0; mt < 2; mt++)
                ldm4(a[mt], aB + (uint32_t)(mt * 16 * 5 + ks * 2) * 16);
#pragma unroll
            for (int p = 0; p < 2; p++) {
                uint32_t off = (uint32_t)(p * 16 * 5 + ks * 2) * 16;
                ldm4(bh + p * 4, bHiB + off);
                ldm4(bl + p * 4, bLoB + off);
            }
#pragma unroll
            for (int mt = 0; mt < 2; mt++) {
#pragma unroll
                for (int nt = 0; nt < 4; nt++) {
                    const uint32_t* bhf = bh + (nt >> 1) * 4 + (nt & 1) * 2;
                    const uint32_t* blf = bl + (nt >> 1) * 4 + (nt & 1) * 2;
                    mma_f16(acc[mt][nt], a[mt], bhf);
                    mma_f16(acc[mt][nt], a[mt], blf);
                }
            }
        }
    }

    const int r0 = rowA0 + warp_m * 32 + (lane >> 2);
    const int c0 = rowB0 + warp_n * 32 + (lane & 3) * 2;
#pragma unroll
    for (int mt = 0; mt < 2; mt++) {
#pragma unroll
        for (int nt = 0; nt < 4; nt++) {
            float* p0 = C + (size_t)(r0 + mt * 16) * ldC + c0 + nt * 8;
            *(float2*)p0 = make_float2(acc[mt][nt][0], acc[mt][nt][1]);
            *(float2*)(p0 + 8 * ldC) = make_float2(acc[mt][nt][2], acc[mt][nt][3]);
        }
    }
}

// ---------------- gates GEMM: CTA 128x64, 256 threads -----------------------
__global__ __launch_bounds__(256, 1) void gemm_f16_64(
    const __half* __restrict__ A,
    const __half* __restrict__ Bhw, const __half* __restrict__ Blw,
    float* __restrict__ C, int ldC)
{
    constexpr int NT = 64;
    constexpr int AUNITS = 128 * 5;
    constexpr int BUNITS = NT * 5;
    constexpr int STAGE_U = AUNITS + 2 * BUNITS;
    constexpr int NSTAGE_K = KD / 32;

    extern __shared__ __align__(16) unsigned char smem[];
    const uint32_t sbase = s2u32(smem);
    const int tid = threadIdx.x;
    const int wid = tid >> 5;
    const int lane = tid & 31;
    const int warp_m = wid >> 1;     // 0..3, WM=32
    const int warp_n = wid & 1;      // 0..1
    const int rowA0 = blockIdx.y * 128;
    const int rowB0 = blockIdx.x * NT;

    float acc[2][4][4];
#pragma unroll
    for (int mt = 0; mt < 2; mt++)
#pragma unroll
        for (int nt = 0; nt < 4; nt++)
#pragma unroll
            for (int j = 0; j < 4; j++) acc[mt][nt][j] = 0.0f;

    auto load_stage = [&](int stage, int kc) {
        uint32_t base = sbase + stage * STAGE_U * 16;
        const int col = kc * 32;
#pragma unroll
        for (int i = 0; i < 2; i++) {
            int idx = tid + i * 256;
            int r = idx >> 2, c = idx & 3;
            uint32_t dst = base + (uint32_t)(r * 5 + c) * 16;
            cpa16(dst, A + (size_t)(rowA0 + r) * KD + col + c * 8);
        }
        {
            int r = tid >> 2, c = tid & 3;
            if (r < NT) {
                uint32_t dst = base + (uint32_t)(AUNITS + r * 5 + c) * 16;
                cpa16(dst, Bhw + (size_t)(rowB0 + r) * KD + col + c * 8);
                cpa16(dst + BUNITS * 16, Blw + (size_t)(rowB0 + r) * KD + col + c * 8);
            }
        }
    };

    const int aRow = lane & 15;
    const int aHalf = (lane >> 4) & 1;
    const int bRow = (lane & 7) + ((lane >> 4) << 3);
    const int bHalf = (lane >> 3) & 1;

    load_stage(0, 0); cpa_commit();
    load_stage(1, 1); cpa_commit();
    load_stage(2, 2); cpa_commit();

#pragma unroll 1
    for (int kc = 0; kc < NSTAGE_K; kc++) {
        cpa_wait<2>();
        __syncthreads();
        if (kc + 3 < NSTAGE_K) load_stage((kc + 3) & 3, kc + 3);
        cpa_commit();

        uint32_t stg = sbase + (kc & 3) * STAGE_U * 16;
        uint32_t aB   = stg + (uint32_t)((warp_m * 32 + aRow) * 5 + aHalf) * 16;
        uint32_t bHiB = stg + (uint32_t)(AUNITS + (warp_n * 32 + bRow) * 5 + bHalf) * 16;
        uint32_t bLoB = bHiB + BUNITS * 16;

#pragma unroll
        for (int ks = 0; ks < 2; ks++) {
            uint32_t a[2][4], bh[8], bl[8];
#pragma unroll
            for (int mt = 0; mt < 2; mt++)
                ldm4(a[mt], aB + (uint32_t)(mt * 16 * 5 + ks * 2) * 16);
#pragma unroll
            for (int p = 0; p < 2; p++) {
                uint32_t off = (uint32_t)(p * 16 * 5 + ks * 2) * 16;
                ldm4(bh + p * 4, bHiB + off);
                ldm4(bl + p * 4, bLoB + off);
            }
#pragma unroll
            for (int mt = 0; mt < 2; mt++) {
#pragma unroll
                for (int nt = 0; nt < 4; nt++) {
                    const uint32_t* bhf = bh + (nt >> 1) * 4 + (nt & 1) * 2;
                    const uint32_t* blf = bl + (nt >> 1) * 4 + (nt & 1) * 2;
                    mma_f16(acc[mt][nt], a[mt], bhf);
                    mma_f16(acc[mt][nt], a[mt], blf);
                }
            }
        }
    }

    const int r0 = rowA0 + warp_m * 32 + (lane >> 2);
    const int c0 = rowB0 + warp_n * 32 + (lane & 3) * 2;
#pragma unroll
    for (int mt = 0; mt < 2; mt++) {
#pragma unroll
        for (int nt = 0; nt < 4; nt++) {
            float* p0 = C + (size_t)(r0 + mt * 16) * ldC + c0 + nt * 8;
            *(float2*)p0 = make_float2(acc[mt][nt][0], acc[mt][nt][1]);
            *(float2*)(p0 + 8 * ldC) = make_float2(acc[mt][nt][2], acc[mt][nt][3]);
        }
    }
}

// ---------------- readout via mma: o = alpha*q@Mf + (1-alpha)*q@Ms ----------
// A = q fp16 [128 l x 64 d], B = Mt fp16 [128 e' x 64 d] (e'<64 fast).
// 256 threads (8 warps x 16 rows), K=64, single-shot smem, blend in epilogue.
__global__ __launch_bounds__(256) void readout_mma(
    const __half* __restrict__ qh, const __half* __restrict__ Mt,
    const float* __restrict__ alp, __half* __restrict__ oh)
{
    __shared__ __align__(16) unsigned char sm[2 * 128 * 9 * 16];   // q | Mt
    const uint32_t sbase = s2u32(sm);
    const uint32_t mbase = sbase + 128 * 9 * 16;
    const int tid = threadIdx.x;
    const int wid = tid >> 5;
    const int lane = tid & 31;
    const int bh = blockIdx.x;
    const int l0 = blockIdx.y * 128;

    // load q tile and M tile (128 rows x 8 chunks each, pad to 9)
#pragma unroll
    for (int i = 0; i < 4; i++) {
        int idx = tid + i * 256;
        int r = idx >> 3, c = idx & 7;
        cpa16(sbase + (uint32_t)(r * 9 + c) * 16,
              qh + ((size_t)bh * Lsz + l0 + r) * 64 + c * 8);
        cpa16(mbase + (uint32_t)(r * 9 + c) * 16,
              Mt + ((size_t)bh * 128 + r) * 64 + c * 8);
    }
    cpa_commit();
    cpa_wait<0>();
    __syncthreads();

    const int aRow = lane & 15;
    const int aHalf = (lane >> 4) & 1;
    const int bRow = (lane & 7) + ((lane >> 4) << 3);
    const int bHalf = (lane >> 3) & 1;

    float acc[16][4];
#pragma unroll
    for (int nt = 0; nt < 16; nt++)
#pragma unroll
        for (int j = 0; j < 4; j++) acc[nt][j] = 0.0f;

#pragma unroll
    for (int ks = 0; ks < 4; ks++) {
        uint32_t a[4];
        ldm4(a, sbase + (uint32_t)((wid * 16 + aRow) * 9 + ks * 2 + aHalf) * 16);
#pragma unroll
        for (int nb = 0; nb < 8; nb++) {
            uint32_t b[4];
            ldm4(b, mbase + (uint32_t)((nb * 16 + bRow) * 9 + ks * 2 + bHalf) * 16);
            mma_f16(acc[nb * 2],     a, b);
            mma_f16(acc[nb * 2 + 1], a, b + 2);
        }
    }

    // epilogue: blend fast/slow, write fp16 o
    const int r0 = wid * 16 + (lane >> 2);
    const float a0 = alp[(size_t)bh * Lsz + l0 + r0];
    const float a1 = alp[(size_t)bh * Lsz + l0 + r0 + 8];
    const int b_ = bh >> 4, h = bh & 15;
    __half* o0 = oh + ((size_t)(b_ * Lsz + l0 + r0)) * Dsz + h * 64 + (lane & 3) * 2;
    __half* o1 = o0 + 8 * Dsz;
#pragma unroll
    for (int nt = 0; nt < 8; nt++) {
        float v0 = a0 * acc[nt][0] + (1.0f - a0) * acc[nt + 8][0];
        float v1 = a0 * acc[nt][1] + (1.0f - a0) * acc[nt + 8][1];
        float v2 = a1 * acc[nt][2] + (1.0f - a1) * acc[nt + 8][2];
        float v3 = a1 * acc[nt][3] + (1.0f - a1) * acc[nt + 8][3];
        *(__half2*)(o0 + nt * 8) = __floats2half2_rn(v0, v1);
        *(__half2*)(o1 + nt * 8) = __floats2half2_rn(v2, v3);
    }
}

// ---------------- prep: x -> fp16 -------------------------------------------
__global__ __launch_bounds__(256) void conv_x(
    const float* __restrict__ x, __half* __restrict__ xh)
{
    int i = blockIdx.x * 256 + threadIdx.x;
    float4 v = ((const float4*)x)[i];
    __half2* o = (__half2*)(xh + i * 4);
    o[0] = __floats2half2_rn(v.x, v.y);
    o[1] = __floats2half2_rn(v.z, v.w);
}

// ---------------- prep: transpose + fp16 hi/lo split of weights -------------
__global__ __launch_bounds__(256) void split_wt(
    const float* __restrict__ W, __half* __restrict__ Bh, __half* __restrict__ Bl,
    int rowOff)
{
    __shared__ float t[32][33];
    int bx = blockIdx.x, by = blockIdx.y;
    int tx = threadIdx.x & 31, ty = threadIdx.x >> 5;
#pragma unroll
    for (int i = 0; i < 4; i++) {
        int k = by * 32 + ty + i * 8;
        t[ty + i * 8][tx] = W[(size_t)k * Dsz + bx * 32 + tx];
    }
    __syncthreads();
#pragma unroll
    for (int i = 0; i < 4; i++) {
        int n = bx * 32 + ty + i * 8 + rowOff;
        float v = t[tx][ty + i * 8];
        __half h = __float2half_rn(v);
        Bh[(size_t)n * Dsz + by * 32 + tx] = h;
        Bl[(size_t)n * Dsz + by * 32 + tx] = __float2half_rn(v - __half2float(h));
    }
}

// ---------------- prep: gate weights ----------------------------------------
__global__ __launch_bounds__(256) void split_gate(
    const float* __restrict__ Wb, const float* __restrict__ Wfd, const float* __restrict__ Wsd,
    __half* __restrict__ Gh, __half* __restrict__ Gl)
{
    int n = blockIdx.x;
    for (int k = threadIdx.x; k < Dsz; k += 256) {
        float v = 0.0f;
        if (n < 16)      v = Wb [k * Hsz + n];
        else if (n < 32) v = Wfd[k * Hsz + (n - 16)];
        else if (n < 48) v = Wsd[k * Hsz + (n - 32)];
        __half h = __float2half_rn(v);
        Gh[(size_t)n * Dsz + k] = h;
        Gl[(size_t)n * Dsz + k] = __float2half_rn(v - __half2float(h));
    }
}

// ---------------- per-(token,head) transform --------------------------------
__global__ __launch_bounds__(256) void transform_k(
    const float* __restrict__ qkv, const float* __restrict__ praw,
    const float* __restrict__ bfd, const float* __restrict__ bsd,
    const float* __restrict__ Wtf1, const float* __restrict__ btf1,
    const float* __restrict__ Wtf2, const float* __restrict__ btf2,
    __half* __restrict__ qh, float* __restrict__ kb, float* __restrict__ vsc,
    float* __restrict__ lgF, float* __restrict__ lgS, float* __restrict__ alp)
{
    __shared__ float sW1[64 * 32];
    __shared__ float sb1[32];
    __shared__ float sW2[32];
    const int tid = threadIdx.x;
    for (int i = tid; i < 2048; i += 256) sW1[i] = Wtf1[i];
    if (tid < 32) { sb1[tid] = btf1[tid]; sW2[tid] = Wtf2[tid]; }
    __syncthreads();

    const int lane = tid & 31;
    const int gw = blockIdx.x * 8 + (tid >> 5);
    const int head = gw & 15;
    const int tok  = gw >> 4;
    const int b = tok >> 12;
    const int l = tok & (Lsz - 1);
    const int bh = b * Hsz + head;
    const unsigned FULL = 0xffffffffu;

    const float* qr = qkv + (size_t)tok * NQKV + head * DKs;
    float q0 = qr[lane], q1 = qr[lane + 32];
    float ss = q0*q0 + q1*q1;
#pragma unroll
    for (int o = 16; o; o >>= 1) ss += __shfl_xor_sync(FULL, ss, o);
    float inv = 1.0f / fmaxf(sqrtf(ss), 1e-12f);
    size_t obase = ((size_t)bh * Lsz + l) * DKs;
    qh[obase + lane]      = __float2half_rn(q0 * inv);
    qh[obase + lane + 32] = __float2half_rn(q1 * inv);

    const float* kr = qr + 1024;
    float k0 = kr[lane], k1 = kr[lane + 32];
    float ks = k0*k0 + k1*k1;
#pragma unroll
    for (int o = 16; o; o >>= 1) ks += __shfl_xor_sync(FULL, ks, o);
    float kinv = 1.0f / fmaxf(sqrtf(ks), 1e-12f);
    float beta = sigmoidf_(praw[(size_t)tok * 64 + head]);
    float kb0 = k0 * kinv * beta;
    float kb1 = k1 * kinv * beta;
    kb[obase + lane]      = kb0;
    kb[obase + lane + 32] = kb1;

    const float* vr = qr + 2048;
    vsc[obase + lane]      = vr[lane]      * beta;
    vsc[obase + lane + 32] = vr[lane + 32] * beta;

    if (lane == 0) {
        float fdl = praw[(size_t)tok * 64 + 16 + head] + bfd[head];
        float sdl = praw[(size_t)tok * 64 + 32 + head] + bsd[head];
        lgF[(size_t)bh * Lsz + l] = logf(sigmoidf_(fdl) + 1e-6f);
        lgS[(size_t)bh * Lsz + l] = logf(sigmoidf_(sdl) + 1e-6f);
    }

    float acc = 0.0f;
#pragma unroll
    for (int i = 0; i < 64; i++) {
        float kbi = __shfl_sync(FULL, (i < 32) ? kb0 : kb1, i & 31);
        acc += kbi * sW1[i * 32 + lane];
    }
    float hmid = acc + sb1[lane];
    hmid = hmid * (1.0f / (1.0f + expf(-hmid)));
    float t = hmid * sW2[lane];
#pragma unroll
    for (int o = 16; o; o >>= 1) t += __shfl_xor_sync(FULL, t, o);
    if (lane == 0) {
        float tf = sigmoidf_(t + btf2[0]);
        tf = fminf(fmaxf(tf, 0.01f), 0.99f);
        alp[(size_t)bh * Lsz + l] = 0.5f + 0.3f * tf;
    }
}

// ---------------- fp64 scan per (b,h) ---------------------------------------
__global__ __launch_bounds__(512) void scan_k(
    const float* __restrict__ lgF, const float* __restrict__ lgS,
    float* __restrict__ wF, float* __restrict__ wS, float* __restrict__ dinv)
{
    __shared__ double sm[512];
    const int bh = blockIdx.x;
    const int tid = threadIdx.x;
    for (int s = 0; s < 2; s++) {
        const float* lg = s ? lgS : lgF;
        float* w = s ? wS : wF;
        size_t base = (size_t)bh * Lsz + tid * 8;
        double loc[8];
        double run = 0.0;
#pragma unroll
        for (int j = 0; j < 8; j++) { run += (double)lg[base + j]; loc[j] = run; }
        sm[tid] = run;
        __syncthreads();
        for (int off = 1; off < 512; off <<= 1) {
            double v = (tid >= off) ? sm[tid - off] : 0.0;
            __syncthreads();
            sm[tid] += v;
            __syncthreads();
        }
        double total = sm[511];
        double excl = sm[tid] - run;
        double wsum = 0.0;
#pragma unroll
        for (int j = 0; j < 8; j++) {
            double wv = exp(total - (excl + loc[j]));
            w[base + j] = (float)wv;
            wsum += wv;
        }
        __syncthreads();
        sm[tid] = wsum;
        __syncthreads();
        for (int off = 256; off; off >>= 1) {
            if (tid < off) sm[tid] += sm[tid + off];
            __syncthreads();
        }
        if (tid == 0) dinv[s * BH + bh] = (float)(1.0 / (sm[0] + 1e-6));
        __syncthreads();
    }
}

// ---------------- state partials --------------------------------------------
__global__ __launch_bounds__(256) void state_partial(
    const float* __restrict__ kb, const float* __restrict__ vsc,
    const float* __restrict__ wF, const float* __restrict__ wS,
    float* __restrict__ Mpart)
{
    __shared__ __align__(16) float skb[32][68];
    __shared__ __align__(16) float svs[32][68];
    __shared__ float swf[32], sws[32];
    const int bh = blockIdx.x, ch = blockIdx.y;
    const int tid = threadIdx.x;
    const int tx = tid & 15, ty = tid >> 4;
    const int lr = tid >> 3, lc0 = (tid & 7) * 8;
    const int LPC = Lsz / NCHUNK;

    unsigned long long acc[4][4];
#pragma unroll
    for (int r = 0; r < 4; r++)
#pragma unroll
        for (int c = 0; c < 4; c++) acc[r][c] = 0ULL;

    const float* kp = kb  + ((size_t)bh * Lsz + ch * LPC) * DKs;
    const float* vp = vsc + ((size_t)bh * Lsz + ch * LPC) * DKs;
    const float* wfp = wF + (size_t)bh * Lsz + ch * LPC;
    const float* wsp = wS + (size_t)bh * Lsz + ch * LPC;

    for (int l0 = 0; l0 < LPC; l0 += 32) {
        *(float4*)&skb[lr][lc0]     = *(const float4*)(kp + (size_t)(l0 + lr) * DKs + lc0);
        *(float4*)&skb[lr][lc0 + 4] = *(const float4*)(kp + (size_t)(l0 + lr) * DKs + lc0 + 4);
        *(float4*)&svs[lr][lc0]     = *(const float4*)(vp + (size_t)(l0 + lr) * DKs + lc0);
        *(float4*)&svs[lr][lc0 + 4] = *(const float4*)(vp + (size_t)(l0 + lr) * DKs + lc0 + 4);
        if (tid < 32) swf[tid] = wfp[l0 + tid];
        else if (tid < 64) sws[tid - 32] = wsp[l0 + tid - 32];
        __syncthreads();
#pragma unroll
        for (int l = 0; l < 32; l++) {
            unsigned long long wpair = pk2(swf[l], sws[l]);
            unsigned long long kw[4], vd[4];
#pragma unroll
            for (int r = 0; r < 4; r++) kw[r] = mul2(pkdup(skb[l][ty*4 + r]), wpair);
#pragma unroll
            for (int c = 0; c < 4; c++) vd[c] = pkdup(svs[l][tx*4 + c]);
#pragma unroll
            for (int r = 0; r < 4; r++)
#pragma unroll
                for (int c = 0; c < 4; c++) fma2(acc[r][c], kw[r], vd[c]);
        }
        __syncthreads();
    }
    size_t base = (size_t)ch * (2 * BH * 4096) + (size_t)bh * 4096;
#pragma unroll
    for (int r = 0; r < 4; r++)
#pragma unroll
        for (int c = 0; c < 4; c++) {
            float2 fs = upk2(acc[r][c]);
            int de = (ty*4 + r) * 64 + (tx*4 + c);
            Mpart[base + de] = fs.x;
            Mpart[base + BH * 4096 + de] = fs.y;
        }
}

// ---------------- reduce partials -> Mt fp16 transposed ----------------------
__global__ __launch_bounds__(256) void reduceM_t(
    const float* __restrict__ Mpart, const float* __restrict__ dinv,
    __half* __restrict__ Mt)
{
    int idx = blockIdx.x * 256 + threadIdx.x;
    if (idx >= 2 * BH * 4096) return;
    float s = 0.0f;
#pragma unroll
    for (int c = 0; c < NCHUNK; c++) s += Mpart[(size_t)c * (2 * BH * 4096) + idx];
    float val = s * dinv[idx >> 12];
    int st = idx >> 17;               // state
    int bh = (idx >> 12) & (BH - 1);
    int de = idx & 4095;
    int d = de >> 6, e = de & 63;
    Mt[((size_t)bh * 128 + st * 64 + e) * 64 + d] = __float2half_rn(val);
}

// ---------------- launch ----------------------------------------------------
extern "C" void kernel_launch(void* const* d_in, const int* in_sizes, int n_in,
                              void* d_out, int out_size)
{
    const float* x    = (const float*)d_in[0];
    const float* Wq   = (const float*)d_in[1];
    const float* Wk   = (const float*)d_in[2];
    const float* Wv   = (const float*)d_in[3];
    const float* Wb   = (const float*)d_in[4];
    const float* Wo   = (const float*)d_in[5];
    const float* Wfd  = (const float*)d_in[6];
    const float* bfd  = (const float*)d_in[7];
    const float* Wsd  = (const float*)d_in[8];
    const float* bsd  = (const float*)d_in[9];
    const float* Wtf1 = (const float*)d_in[10];
    const float* btf1 = (const float*)d_in[11];
    const float* Wtf2 = (const float*)d_in[12];
    const float* btf2 = (const float*)d_in[13];

    float *qkv, *praw, *kb, *vs, *lgf, *lgs, *wf, *ws, *alpha, *dinv, *Mpart;
    __half *xh, *oh, *qh, *Mt, *wqkvh, *wqkvl, *woh, *wol, *wgh, *wgl;
    cudaGetSymbolAddress((void**)&qkv,  g_qkv);
    cudaGetSymbolAddress((void**)&praw, g_praw);
    cudaGetSymbolAddress((void**)&kb,   g_kb);
    cudaGetSymbolAddress((void**)&vs,   g_vs);
    cudaGetSymbolAddress((void**)&lgf,  g_lgf);
    cudaGetSymbolAddress((void**)&lgs,  g_lgs);
    cudaGetSymbolAddress((void**)&wf,   g_wf);
    cudaGetSymbolAddress((void**)&ws,   g_ws);
    cudaGetSymbolAddress((void**)&alpha,g_alpha);
    cudaGetSymbolAddress((void**)&dinv, g_dinv);
    cudaGetSymbolAddress((void**)&Mpart,g_Mpart);
    cudaGetSymbolAddress((void**)&xh,   g_xh);
    cudaGetSymbolAddress((void**)&oh,   g_oh);
    cudaGetSymbolAddress((void**)&qh,   g_qh);
    cudaGetSymbolAddress((void**)&Mt,   g_Mt);
    cudaGetSymbolAddress((void**)&wqkvh,g_wqkvh);
    cudaGetSymbolAddress((void**)&wqkvl,g_wqkvl);
    cudaGetSymbolAddress((void**)&woh,  g_woh);
    cudaGetSymbolAddress((void**)&wol,  g_wol);
    cudaGetSymbolAddress((void**)&wgh,  g_wgh);
    cudaGetSymbolAddress((void**)&wgl,  g_wgl);

    const int SM512 = 4 * (3 * 128 * 5) * 16;                 // 122880
    const int SM64  = 4 * (128 * 5 + 2 * 64 * 5) * 16;        // 81920
    cudaFuncSetAttribute(gemm_f16_512, cudaFuncAttributeMaxDynamicSharedMemorySize, SM512);
    cudaFuncSetAttribute(gemm_f16_64,  cudaFuncAttributeMaxDynamicSharedMemorySize, SM64);

    // prep: exactly 5 launches so QKV GEMM is launch #6 (ncu capture slot)
    conv_x<<<TOK * Dsz / 4 / 256, 256>>>(x, xh);
    dim3 gW(32, 32);
    split_wt<<<gW, 256>>>(Wq, wqkvh, wqkvl, 0);
    split_wt<<<gW, 256>>>(Wk, wqkvh, wqkvl, 1024);
    split_wt<<<gW, 256>>>(Wv, wqkvh, wqkvl, 2048);
    split_gate<<<64, 256>>>(Wb, Wfd, Wsd, wgh, wgl);

    // fused QKV projection — launch #6, captured by ncu
    gemm_f16_512<<<dim3(NQKV / 128, TOK / 128), 512, SM512>>>(xh, wqkvh, wqkvl, qkv, NQKV);

    split_wt<<<gW, 256>>>(Wo, woh, wol, 0);
    gemm_f16_64<<<dim3(1, TOK / 128), 256, SM64>>>(xh, wgh, wgl, praw, 64);

    transform_k<<<TOK * Hsz / 8, 256>>>(qkv, praw, bfd, bsd,
                                        Wtf1, btf1, Wtf2, btf2,
                                        qh, kb, vs, lgf, lgs, alpha);
    scan_k<<<BH, 512>>>(lgf, lgs, wf, ws, dinv);
    state_partial<<<dim3(BH, NCHUNK), 256>>>(kb, vs, wf, ws, Mpart);
    reduceM_t<<<(2 * BH * 4096 + 255) / 256, 256>>>(Mpart, dinv, Mt);
    readout_mma<<<dim3(BH, Lsz / 128), 256>>>(qh, Mt, alpha, oh);

    gemm_f16_512<<<dim3(Dsz / 128, TOK / 128), 512, SM512>>>(oh, woh, wol, (float*)d_out, Dsz);
}

// round 9
// speedup vs baseline: 1.3088x; 1.0665x over previous
#include <cuda_runtime.h>
#include <cuda_fp16.h>
#include <math.h>
#include <cstdint>

// Problem constants
#define Bsz 2
#define Lsz 4096
#define Dsz 1024
#define Hsz 16
#define DKs 64
#define TOK (Bsz*Lsz)          // 8192
#define BH  (Bsz*Hsz)          // 32
#define NCHUNK 8               // state-mma l chunks (512 l each)
#define KD 1024                // GEMM K
#define NQKV 3072

// ---------------- scratch ---------------------------------------------------
__device__ float g_qkv [TOK*NQKV];     // fused q|k|v raw projections
__device__ float g_praw[TOK*64];
__device__ float g_vs  [TOK*Dsz];      // v*beta fp32, [bh][l][64]
__device__ float g_lgf [BH*Lsz];
__device__ float g_lgs [BH*Lsz];
__device__ float g_wf  [BH*Lsz];
__device__ float g_ws  [BH*Lsz];
__device__ float g_alpha[BH*Lsz];
__device__ float g_dinv[2*BH];
__device__ float g_Mpart[NCHUNK*2*BH*DKs*DKs];
// fp16 operands
__device__ __half g_xh[TOK*Dsz];
__device__ __half g_oh[TOK*Dsz];
__device__ __half g_qh[TOK*Dsz];       // q normalized, [bh][l][64]
__device__ __half g_kbh[TOK*Dsz];      // k_beta fp16, [bh][l][64]
__device__ __half g_Mt[BH*128*DKs];    // M transposed: [bh][e'(0..127)][d], e'<64 fast
__device__ __half g_wqkvh[NQKV*Dsz], g_wqkvl[NQKV*Dsz];
__device__ __half g_woh[Dsz*Dsz], g_wol[Dsz*Dsz];
__device__ __half g_wgh[64*Dsz],  g_wgl[64*Dsz];

__device__ __forceinline__ float sigmoidf_(float x) { return 1.0f / (1.0f + expf(-x)); }

// ---------------- mma.sync helpers ------------------------------------------
__device__ __forceinline__ uint32_t s2u32(const void* p) {
    uint32_t a;
    asm("{ .reg .u64 t; cvta.to.shared.u64 t, %1; cvt.u32.u64 %0, t; }" : "=r"(a) : "l"(p));
    return a;
}
__device__ __forceinline__ void cpa16(uint32_t s, const void* g) {
    asm volatile("cp.async.cg.shared.global [%0], [%1], 16;" :: "r"(s), "l"(g));
}
__device__ __forceinline__ void cpa_commit() { asm volatile("cp.async.commit_group;" ::: "memory"); }
template<int N> __device__ __forceinline__ void cpa_wait() { asm volatile("cp.async.wait_group %0;" :: "n"(N) : "memory"); }

__device__ __forceinline__ void ldm4(uint32_t* r, uint32_t addr) {
    asm volatile("ldmatrix.sync.aligned.m8n8.x4.shared.b16 {%0,%1,%2,%3}, [%4];"
        : "=r"(r[0]), "=r"(r[1]), "=r"(r[2]), "=r"(r[3]) : "r"(addr));
}
__device__ __forceinline__ void ldm4t(uint32_t* r, uint32_t addr) {
    asm volatile("ldmatrix.sync.aligned.m8n8.x4.trans.shared.b16 {%0,%1,%2,%3}, [%4];"
        : "=r"(r[0]), "=r"(r[1]), "=r"(r[2]), "=r"(r[3]) : "r"(addr));
}
__device__ __forceinline__ void mma_f16(float* d, const uint32_t* a, const uint32_t* b) {
    asm volatile(
        "mma.sync.aligned.m16n8k16.row.col.f32.f16.f16.f32 "
        "{%0,%1,%2,%3}, {%4,%5,%6,%7}, {%8,%9}, {%0,%1,%2,%3};"
        : "+f"(d[0]), "+f"(d[1]), "+f"(d[2]), "+f"(d[3])
        : "r"(a[0]), "r"(a[1]), "r"(a[2]), "r"(a[3]), "r"(b[0]), "r"(b[1]));
}

// ---------------- big GEMM: C = A @ (Bh+Bl)^T, A fp16, 2-term, f32 acc ------
// 512 threads, CTA 128x128, warp tile 32x32, 4-stage cp.async pipeline.
__global__ __launch_bounds__(512, 1) void gemm_f16_512(
    const __half* __restrict__ A,
    const __half* __restrict__ Bhw, const __half* __restrict__ Blw,
    float* __restrict__ C, int ldC)
{
    constexpr int UNITS = 128 * 5;            // 16B units per tile
    constexpr int STAGE_U = 3 * UNITS;        // A | Bh | Bl
    constexpr int NSTAGE_K = KD / 32;         // 32

    extern __shared__ __align__(16) unsigned char smem[];
    const uint32_t sbase = s2u32(smem);
    const int tid = threadIdx.x;
    const int wid = tid >> 5;
    const int lane = tid & 31;
    const int warp_m = wid >> 2;              // 0..3
    const int warp_n = wid & 3;               // 0..3
    const int rowA0 = blockIdx.y * 128;
    const int rowB0 = blockIdx.x * 128;

    float acc[2][4][4];
#pragma unroll
    for (int mt = 0; mt < 2; mt++)
#pragma unroll
        for (int nt = 0; nt < 4; nt++)
#pragma unroll
            for (int j = 0; j < 4; j++) acc[mt][nt][j] = 0.0f;

    auto load_stage = [&](int stage, int kc) {
        uint32_t base = sbase + stage * STAGE_U * 16;
        const int col = kc * 32;
        int r = tid >> 2, c = tid & 3;
        uint32_t dst = base + (uint32_t)(r * 5 + c) * 16;
        cpa16(dst, A + (size_t)(rowA0 + r) * KD + col + c * 8);
        cpa16(dst + UNITS * 16,     Bhw + (size_t)(rowB0 + r) * KD + col + c * 8);
        cpa16(dst + 2 * UNITS * 16, Blw + (size_t)(rowB0 + r) * KD + col + c * 8);
    };

    const int aRow = lane & 15;
    const int aHalf = (lane >> 4) & 1;
    const int bRow = (lane & 7) + ((lane >> 4) << 3);
    const int bHalf = (lane >> 3) & 1;

    load_stage(0, 0); cpa_commit();
    load_stage(1, 1); cpa_commit();
    load_stage(2, 2); cpa_commit();

#pragma unroll 1
    for (int kc = 0; kc < NSTAGE_K; kc++) {
        cpa_wait<2>();
        __syncthreads();
        if (kc + 3 < NSTAGE_K) load_stage((kc + 3) & 3, kc + 3);
        cpa_commit();

        uint32_t stg = sbase + (kc & 3) * STAGE_U * 16;
        uint32_t aB   = stg + (uint32_t)((warp_m * 32 + aRow) * 5 + aHalf) * 16;
        uint32_t bHiB = stg + (uint32_t)(UNITS + (warp_n * 32 + bRow) * 5 + bHalf) * 16;
        uint32_t bLoB = bHiB + UNITS * 16;

#pragma unroll
        for (int ks = 0; ks < 2; ks++) {
            uint32_t a[2][4], bh[8], bl[8];
#pragma unroll
            for (int mt = 0; mt < 2; mt++)
                ldm4(a[mt], aB + (uint32_t)(mt * 16 * 5 + ks * 2) * 16);
#pragma unroll
            for (int p = 0; p < 2; p++) {
                uint32_t off = (uint32_t)(p * 16 * 5 + ks * 2) * 16;
                ldm4(bh + p * 4, bHiB + off);
                ldm4(bl + p * 4, bLoB + off);
            }
#pragma unroll
            for (int mt = 0; mt < 2; mt++) {
#pragma unroll
                for (int nt = 0; nt < 4; nt++) {
                    const uint32_t* bhf = bh + (nt >> 1) * 4 + (nt & 1) * 2;
                    const uint32_t* blf = bl + (nt >> 1) * 4 + (nt & 1) * 2;
                    mma_f16(acc[mt][nt], a[mt], bhf);
                    mma_f16(acc[mt][nt], a[mt], blf);
                }
            }
        }
    }

    const int r0 = rowA0 + warp_m * 32 + (lane >> 2);
    const int c0 = rowB0 + warp_n * 32 + (lane & 3) * 2;
#pragma unroll
    for (int mt = 0; mt < 2; mt++) {
#pragma unroll
        for (int nt = 0; nt < 4; nt++) {
            float* p0 = C + (size_t)(r0 + mt * 16) * ldC + c0 + nt * 8;
            *(float2*)p0 = make_float2(acc[mt][nt][0], acc[mt][nt][1]);
            *(float2*)(p0 + 8 * ldC) = make_float2(acc[mt][nt][2], acc[mt][nt][3]);
        }
    }
}

// ---------------- gates GEMM: CTA 128x64, 256 threads -----------------------
__global__ __launch_bounds__(256, 1) void gemm_f16_64(
    const __half* __restrict__ A,
    const __half* __restrict__ Bhw, const __half* __restrict__ Blw,
    float* __restrict__ C, int ldC)
{
    constexpr int NT = 64;
    constexpr int AUNITS = 128 * 5;
    constexpr int BUNITS = NT * 5;
    constexpr int STAGE_U = AUNITS + 2 * BUNITS;
    constexpr int NSTAGE_K = KD / 32;

    extern __shared__ __align__(16) unsigned char smem[];
    const uint32_t sbase = s2u32(smem);
    const int tid = threadIdx.x;
    const int wid = tid >> 5;
    const int lane = tid & 31;
    const int warp_m = wid >> 1;
    const int warp_n = wid & 1;
    const int rowA0 = blockIdx.y * 128;
    const int rowB0 = blockIdx.x * NT;

    float acc[2][4][4];
#pragma unroll
    for (int mt = 0; mt < 2; mt++)
#pragma unroll
        for (int nt = 0; nt < 4; nt++)
#pragma unroll
            for (int j = 0; j < 4; j++) acc[mt][nt][j] = 0.0f;

    auto load_stage = [&](int stage, int kc) {
        uint32_t base = sbase + stage * STAGE_U * 16;
        const int col = kc * 32;
#pragma unroll
        for (int i = 0; i < 2; i++) {
            int idx = tid + i * 256;
            int r = idx >> 2, c = idx & 3;
            uint32_t dst = base + (uint32_t)(r * 5 + c) * 16;
            cpa16(dst, A + (size_t)(rowA0 + r) * KD + col + c * 8);
        }
        {
            int r = tid >> 2, c = tid & 3;
            if (r < NT) {
                uint32_t dst = base + (uint32_t)(AUNITS + r * 5 + c) * 16;
                cpa16(dst, Bhw + (size_t)(rowB0 + r) * KD + col + c * 8);
                cpa16(dst + BUNITS * 16, Blw + (size_t)(rowB0 + r) * KD + col + c * 8);
            }
        }
    };

    const int aRow = lane & 15;
    const int aHalf = (lane >> 4) & 1;
    const int bRow = (lane & 7) + ((lane >> 4) << 3);
    const int bHalf = (lane >> 3) & 1;

    load_stage(0, 0); cpa_commit();
    load_stage(1, 1); cpa_commit();
    load_stage(2, 2); cpa_commit();

#pragma unroll 1
    for (int kc = 0; kc < NSTAGE_K; kc++) {
        cpa_wait<2>();
        __syncthreads();
        if (kc + 3 < NSTAGE_K) load_stage((kc + 3) & 3, kc + 3);
        cpa_commit();

        uint32_t stg = sbase + (kc & 3) * STAGE_U * 16;
        uint32_t aB   = stg + (uint32_t)((warp_m * 32 + aRow) * 5 + aHalf) * 16;
        uint32_t bHiB = stg + (uint32_t)(AUNITS + (warp_n * 32 + bRow) * 5 + bHalf) * 16;
        uint32_t bLoB = bHiB + BUNITS * 16;

#pragma unroll
        for (int ks = 0; ks < 2; ks++) {
            uint32_t a[2][4], bh[8], bl[8];
#pragma unroll
            for (int mt = 0; mt < 2; mt++)
                ldm4(a[mt], aB + (uint32_t)(mt * 16 * 5 + ks * 2) * 16);
#pragma unroll
            for (int p = 0; p < 2; p++) {
                uint32_t off = (uint32_t)(p * 16 * 5 + ks * 2) * 16;
                ldm4(bh + p * 4, bHiB + off);
                ldm4(bl + p * 4, bLoB + off);
            }
#pragma unroll
            for (int mt = 0; mt < 2; mt++) {
#pragma unroll
                for (int nt = 0; nt < 4; nt++) {
                    const uint32_t* bhf = bh + (nt >> 1) * 4 + (nt & 1) * 2;
                    const uint32_t* blf = bl + (nt >> 1) * 4 + (nt & 1) * 2;
                    mma_f16(acc[mt][nt], a[mt], bhf);
                    mma_f16(acc[mt][nt], a[mt], blf);
                }
            }
        }
    }

    const int r0 = rowA0 + warp_m * 32 + (lane >> 2);
    const int c0 = rowB0 + warp_n * 32 + (lane & 3) * 2;
#pragma unroll
    for (int mt = 0; mt < 2; mt++) {
#pragma unroll
        for (int nt = 0; nt < 4; nt++) {
            float* p0 = C + (size_t)(r0 + mt * 16) * ldC + c0 + nt * 8;
            *(float2*)p0 = make_float2(acc[mt][nt][0], acc[mt][nt][1]);
            *(float2*)(p0 + 8 * ldC) = make_float2(acc[mt][nt][2], acc[mt][nt][3]);
        }
    }
}

// ---------------- state via mma: M[d][e] = sum_l kb[l][d] * (v*w)[l][e] -----
// Per (bh, chunk of 512 l). A = kb (trans ldmatrix), B = v*wf / v*ws (trans).
// 128 threads (4 warps x 16 d-rows). fp32 partials to Mpart.
__global__ __launch_bounds__(128) void state_mma(
    const __half* __restrict__ kbh, const float* __restrict__ vsc,
    const float* __restrict__ wF, const float* __restrict__ wS,
    float* __restrict__ Mpart)
{
    extern __shared__ __align__(16) unsigned char sm[];
    const uint32_t kb_b = s2u32(sm);                // [128][9*16B]
    const uint32_t vf_b = kb_b + 128 * 144;
    const uint32_t vs_b = vf_b + 128 * 144;
    const int tid = threadIdx.x;
    const int wid = tid >> 5;
    const int lane = tid & 31;
    const int bh = blockIdx.x, ch = blockIdx.y;

    float accF[8][4], accS[8][4];
#pragma unroll
    for (int nt = 0; nt < 8; nt++)
#pragma unroll
        for (int j = 0; j < 4; j++) { accF[nt][j] = 0.0f; accS[nt][j] = 0.0f; }

    // A-trans lane mapping: stored rows = l, cols = d
    const int lA = (lane & 7) + ((lane >> 4) << 3);
    const int dOffB = wid * 32 + ((lane >> 3) & 1) * 16;   // bytes
    // B-trans lane mapping: stored rows = l, cols = e
    const int lB = lane & 15;
    const int eOffB = (lane >> 4) * 16;                     // bytes

#pragma unroll 1
    for (int it = 0; it < 4; it++) {
        const int l0 = ch * 512 + it * 128;
        if (it) __syncthreads();
        // kb tile via cp.async: 128 rows x 8 chunks
#pragma unroll
        for (int i = 0; i < 8; i++) {
            int idx = tid + i * 128;
            int r = idx >> 3, c = idx & 7;
            cpa16(kb_b + (uint32_t)(r * 144 + c * 16),
                  kbh + ((size_t)bh * Lsz + l0 + r) * 64 + c * 8);
        }
        cpa_commit();
        // v*w tiles: thread t owns row t
        {
            const int r = tid;
            const float wf = wF[(size_t)bh * Lsz + l0 + r];
            const float wsl = wS[(size_t)bh * Lsz + l0 + r];
            const float4* vp = (const float4*)(vsc + ((size_t)bh * Lsz + l0 + r) * 64);
            __half2* df = (__half2*)(sm + 128 * 144 + r * 144);
            __half2* ds = (__half2*)(sm + 2 * 128 * 144 + r * 144);
#pragma unroll
            for (int c = 0; c < 16; c++) {
                float4 v4 = vp[c];
                df[c * 2]     = __floats2half2_rn(v4.x * wf,  v4.y * wf);
                df[c * 2 + 1] = __floats2half2_rn(v4.z * wf,  v4.w * wf);
                ds[c * 2]     = __floats2half2_rn(v4.x * wsl, v4.y * wsl);
                ds[c * 2 + 1] = __floats2half2_rn(v4.z * wsl, v4.w * wsl);
            }
        }
        cpa_wait<0>();
        __syncthreads();

#pragma unroll
        for (int ks = 0; ks < 8; ks++) {
            uint32_t a[4];
            ldm4t(a, kb_b + (uint32_t)((ks * 16 + lA) * 144 + dOffB));
#pragma unroll
            for (int nb = 0; nb < 4; nb++) {
                uint32_t bf[4], bs[4];
                uint32_t off = (uint32_t)((ks * 16 + lB) * 144 + nb * 32 + eOffB);
                ldm4t(bf, vf_b + off);
                ldm4t(bs, vs_b + off);
                mma_f16(accF[nb * 2],     a, bf);
                mma_f16(accF[nb * 2 + 1], a, bf + 2);
                mma_f16(accS[nb * 2],     a, bs);
                mma_f16(accS[nb * 2 + 1], a, bs + 2);
            }
        }
    }

    // partials: Mpart[ch][state][bh][d*64+e]
    const size_t baseF = ((size_t)ch * 2 + 0) * (BH * 4096) + (size_t)bh * 4096;
    const size_t baseS = ((size_t)ch * 2 + 1) * (BH * 4096) + (size_t)bh * 4096;
    const int d0 = wid * 16 + (lane >> 2);
    const int e0 = (lane & 3) * 2;
#pragma unroll
    for (int nt = 0; nt < 8; nt++) {
        int e = nt * 8 + e0;
        *(float2*)&Mpart[baseF + (size_t)d0 * 64 + e]       = make_float2(accF[nt][0], accF[nt][1]);
        *(float2*)&Mpart[baseF + (size_t)(d0 + 8) * 64 + e] = make_float2(accF[nt][2], accF[nt][3]);
        *(float2*)&Mpart[baseS + (size_t)d0 * 64 + e]       = make_float2(accS[nt][0], accS[nt][1]);
        *(float2*)&Mpart[baseS + (size_t)(d0 + 8) * 64 + e] = make_float2(accS[nt][2], accS[nt][3]);
    }
}

// ---------------- readout via mma: o = alpha*q@Mf + (1-alpha)*q@Ms ----------
__global__ __launch_bounds__(256) void readout_mma(
    const __half* __restrict__ qh, const __half* __restrict__ Mt,
    const float* __restrict__ alp, __half* __restrict__ oh)
{
    __shared__ __align__(16) unsigned char sm[2 * 128 * 9 * 16];   // q | Mt
    const uint32_t sbase = s2u32(sm);
    const uint32_t mbase = sbase + 128 * 9 * 16;
    const int tid = threadIdx.x;
    const int wid = tid >> 5;
    const int lane = tid & 31;
    const int bh = blockIdx.x;
    const int l0 = blockIdx.y * 128;

#pragma unroll
    for (int i = 0; i < 4; i++) {
        int idx = tid + i * 256;
        int r = idx >> 3, c = idx & 7;
        cpa16(sbase + (uint32_t)(r * 9 + c) * 16,
              qh + ((size_t)bh * Lsz + l0 + r) * 64 + c * 8);
        cpa16(mbase + (uint32_t)(r * 9 + c) * 16,
              Mt + ((size_t)bh * 128 + r) * 64 + c * 8);
    }
    cpa_commit();
    cpa_wait<0>();
    __syncthreads();

    const int aRow = lane & 15;
    const int aHalf = (lane >> 4) & 1;
    const int bRow = (lane & 7) + ((lane >> 4) << 3);
    const int bHalf = (lane >> 3) & 1;

    float acc[16][4];
#pragma unroll
    for (int nt = 0; nt < 16; nt++)
#pragma unroll
        for (int j = 0; j < 4; j++) acc[nt][j] = 0.0f;

#pragma unroll
    for (int ks = 0; ks < 4; ks++) {
        uint32_t a[4];
        ldm4(a, sbase + (uint32_t)((wid * 16 + aRow) * 9 + ks * 2 + aHalf) * 16);
#pragma unroll
        for (int nb = 0; nb < 8; nb++) {
            uint32_t b[4];
            ldm4(b, mbase + (uint32_t)((nb * 16 + bRow) * 9 + ks * 2 + bHalf) * 16);
            mma_f16(acc[nb * 2],     a, b);
            mma_f16(acc[nb * 2 + 1], a, b + 2);
        }
    }

    const int r0 = wid * 16 + (lane >> 2);
    const float a0 = alp[(size_t)bh * Lsz + l0 + r0];
    const float a1 = alp[(size_t)bh * Lsz + l0 + r0 + 8];
    const int b_ = bh >> 4, h = bh & 15;
    __half* o0 = oh + ((size_t)(b_ * Lsz + l0 + r0)) * Dsz + h * 64 + (lane & 3) * 2;
    __half* o1 = o0 + 8 * Dsz;
#pragma unroll
    for (int nt = 0; nt < 8; nt++) {
        float v0 = a0 * acc[nt][0] + (1.0f - a0) * acc[nt + 8][0];
        float v1 = a0 * acc[nt][1] + (1.0f - a0) * acc[nt + 8][1];
        float v2 = a1 * acc[nt][2] + (1.0f - a1) * acc[nt + 8][2];
        float v3 = a1 * acc[nt][3] + (1.0f - a1) * acc[nt + 8][3];
        *(__half2*)(o0 + nt * 8) = __floats2half2_rn(v0, v1);
        *(__half2*)(o1 + nt * 8) = __floats2half2_rn(v2, v3);
    }
}

// ---------------- prep: x -> fp16 -------------------------------------------
__global__ __launch_bounds__(256) void conv_x(
    const float* __restrict__ x, __half* __restrict__ xh)
{
    int i = blockIdx.x * 256 + threadIdx.x;
    float4 v = ((const float4*)x)[i];
    __half2* o = (__half2*)(xh + i * 4);
    o[0] = __floats2half2_rn(v.x, v.y);
    o[1] = __floats2half2_rn(v.z, v.w);
}

// ---------------- prep: transpose + fp16 hi/lo split of weights -------------
__global__ __launch_bounds__(256) void split_wt(
    const float* __restrict__ W, __half* __restrict__ Bh, __half* __restrict__ Bl,
    int rowOff)
{
    __shared__ float t[32][33];
    int bx = blockIdx.x, by = blockIdx.y;
    int tx = threadIdx.x & 31, ty = threadIdx.x >> 5;
#pragma unroll
    for (int i = 0; i < 4; i++) {
        int k = by * 32 + ty + i * 8;
        t[ty + i * 8][tx] = W[(size_t)k * Dsz + bx * 32 + tx];
    }
    __syncthreads();
#pragma unroll
    for (int i = 0; i < 4; i++) {
        int n = bx * 32 + ty + i * 8 + rowOff;
        float v = t[tx][ty + i * 8];
        __half h = __float2half_rn(v);
        Bh[(size_t)n * Dsz + by * 32 + tx] = h;
        Bl[(size_t)n * Dsz + by * 32 + tx] = __float2half_rn(v - __half2float(h));
    }
}

// ---------------- prep: gate weights ----------------------------------------
__global__ __launch_bounds__(256) void split_gate(
    const float* __restrict__ Wb, const float* __restrict__ Wfd, const float* __restrict__ Wsd,
    __half* __restrict__ Gh, __half* __restrict__ Gl)
{
    int n = blockIdx.x;
    for (int k = threadIdx.x; k < Dsz; k += 256) {
        float v = 0.0f;
        if (n < 16)      v = Wb [k * Hsz + n];
        else if (n < 32) v = Wfd[k * Hsz + (n - 16)];
        else if (n < 48) v = Wsd[k * Hsz + (n - 32)];
        __half h = __float2half_rn(v);
        Gh[(size_t)n * Dsz + k] = h;
        Gl[(size_t)n * Dsz + k] = __float2half_rn(v - __half2float(h));
    }
}

// ---------------- per-(token,head) transform --------------------------------
__global__ __launch_bounds__(256) void transform_k(
    const float* __restrict__ qkv, const float* __restrict__ praw,
    const float* __restrict__ bfd, const float* __restrict__ bsd,
    const float* __restrict__ Wtf1, const float* __restrict__ btf1,
    const float* __restrict__ Wtf2, const float* __restrict__ btf2,
    __half* __restrict__ qh, __half* __restrict__ kbh, float* __restrict__ vsc,
    float* __restrict__ lgF, float* __restrict__ lgS, float* __restrict__ alp)
{
    __shared__ float sW1[64 * 32];
    __shared__ float sb1[32];
    __shared__ float sW2[32];
    const int tid = threadIdx.x;
    for (int i = tid; i < 2048; i += 256) sW1[i] = Wtf1[i];
    if (tid < 32) { sb1[tid] = btf1[tid]; sW2[tid] = Wtf2[tid]; }
    __syncthreads();

    const int lane = tid & 31;
    const int gw = blockIdx.x * 8 + (tid >> 5);
    const int head = gw & 15;
    const int tok  = gw >> 4;
    const int b = tok >> 12;
    const int l = tok & (Lsz - 1);
    const int bh = b * Hsz + head;
    const unsigned FULL = 0xffffffffu;

    const float* qr = qkv + (size_t)tok * NQKV + head * DKs;
    float q0 = qr[lane], q1 = qr[lane + 32];
    float ss = q0*q0 + q1*q1;
#pragma unroll
    for (int o = 16; o; o >>= 1) ss += __shfl_xor_sync(FULL, ss, o);
    float inv = 1.0f / fmaxf(sqrtf(ss), 1e-12f);
    size_t obase = ((size_t)bh * Lsz + l) * DKs;
    qh[obase + lane]      = __float2half_rn(q0 * inv);
    qh[obase + lane + 32] = __float2half_rn(q1 * inv);

    const float* kr = qr + 1024;
    float k0 = kr[lane], k1 = kr[lane + 32];
    float ks = k0*k0 + k1*k1;
#pragma unroll
    for (int o = 16; o; o >>= 1) ks += __shfl_xor_sync(FULL, ks, o);
    float kinv = 1.0f / fmaxf(sqrtf(ks), 1e-12f);
    float beta = sigmoidf_(praw[(size_t)tok * 64 + head]);
    float kb0 = k0 * kinv * beta;
    float kb1 = k1 * kinv * beta;
    kbh[obase + lane]      = __float2half_rn(kb0);
    kbh[obase + lane + 32] = __float2half_rn(kb1);

    const float* vr = qr + 2048;
    vsc[obase + lane]      = vr[lane]      * beta;
    vsc[obase + lane + 32] = vr[lane + 32] * beta;

    if (lane == 0) {
        float fdl = praw[(size_t)tok * 64 + 16 + head] + bfd[head];
        float sdl = praw[(size_t)tok * 64 + 32 + head] + bsd[head];
        lgF[(size_t)bh * Lsz + l] = logf(sigmoidf_(fdl) + 1e-6f);
        lgS[(size_t)bh * Lsz + l] = logf(sigmoidf_(sdl) + 1e-6f);
    }

    float acc = 0.0f;
#pragma unroll
    for (int i = 0; i < 64; i++) {
        float kbi = __shfl_sync(FULL, (i < 32) ? kb0 : kb1, i & 31);
        acc += kbi * sW1[i * 32 + lane];
    }
    float hmid = acc + sb1[lane];
    hmid = hmid * (1.0f / (1.0f + expf(-hmid)));
    float t = hmid * sW2[lane];
#pragma unroll
    for (int o = 16; o; o >>= 1) t += __shfl_xor_sync(FULL, t, o);
    if (lane == 0) {
        float tf = sigmoidf_(t + btf2[0]);
        tf = fminf(fmaxf(tf, 0.01f), 0.99f);
        alp[(size_t)bh * Lsz + l] = 0.5f + 0.3f * tf;
    }
}

// ---------------- fp64 scan per (b,h) ---------------------------------------
__global__ __launch_bounds__(512) void scan_k(
    const float* __restrict__ lgF, const float* __restrict__ lgS,
    float* __restrict__ wF, float* __restrict__ wS, float* __restrict__ dinv)
{
    __shared__ double sm[512];
    const int bh = blockIdx.x;
    const int tid = threadIdx.x;
    for (int s = 0; s < 2; s++) {
        const float* lg = s ? lgS : lgF;
        float* w = s ? wS : wF;
        size_t base = (size_t)bh * Lsz + tid * 8;
        double loc[8];
        double run = 0.0;
#pragma unroll
        for (int j = 0; j < 8; j++) { run += (double)lg[base + j]; loc[j] = run; }
        sm[tid] = run;
        __syncthreads();
        for (int off = 1; off < 512; off <<= 1) {
            double v = (tid >= off) ? sm[tid - off] : 0.0;
            __syncthreads();
            sm[tid] += v;
            __syncthreads();
        }
        double total = sm[511];
        double excl = sm[tid] - run;
        double wsum = 0.0;
#pragma unroll
        for (int j = 0; j < 8; j++) {
            double wv = exp(total - (excl + loc[j]));
            w[base + j] = (float)wv;
            wsum += wv;
        }
        __syncthreads();
        sm[tid] = wsum;
        __syncthreads();
        for (int off = 256; off; off >>= 1) {
            if (tid < off) sm[tid] += sm[tid + off];
            __syncthreads();
        }
        if (tid == 0) dinv[s * BH + bh] = (float)(1.0 / (sm[0] + 1e-6));
        __syncthreads();
    }
}

// ---------------- reduce partials -> Mt fp16 transposed ----------------------
__global__ __launch_bounds__(256) void reduceM_t(
    const float* __restrict__ Mpart, const float* __restrict__ dinv,
    __half* __restrict__ Mt)
{
    int idx = blockIdx.x * 256 + threadIdx.x;
    if (idx >= 2 * BH * 4096) return;
    float s = 0.0f;
#pragma unroll
    for (int c = 0; c < NCHUNK; c++) s += Mpart[(size_t)c * (2 * BH * 4096) + idx];
    float val = s * dinv[idx >> 12];
    int st = idx >> 17;               // state
    int bh = (idx >> 12) & (BH - 1);
    int de = idx & 4095;
    int d = de >> 6, e = de & 63;
    Mt[((size_t)bh * 128 + st * 64 + e) * 64 + d] = __float2half_rn(val);
}

// ---------------- launch ----------------------------------------------------
extern "C" void kernel_launch(void* const* d_in, const int* in_sizes, int n_in,
                              void* d_out, int out_size)
{
    const float* x    = (const float*)d_in[0];
    const float* Wq   = (const float*)d_in[1];
    const float* Wk   = (const float*)d_in[2];
    const float* Wv   = (const float*)d_in[3];
    const float* Wb   = (const float*)d_in[4];
    const float* Wo   = (const float*)d_in[5];
    const float* Wfd  = (const float*)d_in[6];
    const float* bfd  = (const float*)d_in[7];
    const float* Wsd  = (const float*)d_in[8];
    const float* bsd  = (const float*)d_in[9];
    const float* Wtf1 = (const float*)d_in[10];
    const float* btf1 = (const float*)d_in[11];
    const float* Wtf2 = (const float*)d_in[12];
    const float* btf2 = (const float*)d_in[13];

    float *qkv, *praw, *vs, *lgf, *lgs, *wf, *ws, *alpha, *dinv, *Mpart;
    __half *xh, *oh, *qh, *kbh, *Mt, *wqkvh, *wqkvl, *woh, *wol, *wgh, *wgl;
    cudaGetSymbolAddress((void**)&qkv,  g_qkv);
    cudaGetSymbolAddress((void**)&praw, g_praw);
    cudaGetSymbolAddress((void**)&vs,   g_vs);
    cudaGetSymbolAddress((void**)&lgf,  g_lgf);
    cudaGetSymbolAddress((void**)&lgs,  g_lgs);
    cudaGetSymbolAddress((void**)&wf,   g_wf);
    cudaGetSymbolAddress((void**)&ws,   g_ws);
    cudaGetSymbolAddress((void**)&alpha,g_alpha);
    cudaGetSymbolAddress((void**)&dinv, g_dinv);
    cudaGetSymbolAddress((void**)&Mpart,g_Mpart);
    cudaGetSymbolAddress((void**)&xh,   g_xh);
    cudaGetSymbolAddress((void**)&oh,   g_oh);
    cudaGetSymbolAddress((void**)&qh,   g_qh);
    cudaGetSymbolAddress((void**)&kbh,  g_kbh);
    cudaGetSymbolAddress((void**)&Mt,   g_Mt);
    cudaGetSymbolAddress((void**)&wqkvh,g_wqkvh);
    cudaGetSymbolAddress((void**)&wqkvl,g_wqkvl);
    cudaGetSymbolAddress((void**)&woh,  g_woh);
    cudaGetSymbolAddress((void**)&wol,  g_wol);
    cudaGetSymbolAddress((void**)&wgh,  g_wgh);
    cudaGetSymbolAddress((void**)&wgl,  g_wgl);

    const int SM512 = 4 * (3 * 128 * 5) * 16;                 // 122880
    const int SM64  = 4 * (128 * 5 + 2 * 64 * 5) * 16;        // 81920
    const int SMST  = 3 * 128 * 144;                          // 55296
    cudaFuncSetAttribute(gemm_f16_512, cudaFuncAttributeMaxDynamicSharedMemorySize, SM512);
    cudaFuncSetAttribute(gemm_f16_64,  cudaFuncAttributeMaxDynamicSharedMemorySize, SM64);
    cudaFuncSetAttribute(state_mma,    cudaFuncAttributeMaxDynamicSharedMemorySize, SMST);

    // prep: exactly 5 launches so QKV GEMM is launch #6 (ncu capture slot)
    conv_x<<<TOK * Dsz / 4 / 256, 256>>>(x, xh);
    dim3 gW(32, 32);
    split_wt<<<gW, 256>>>(Wq, wqkvh, wqkvl, 0);
    split_wt<<<gW, 256>>>(Wk, wqkvh, wqkvl, 1024);
    split_wt<<<gW, 256>>>(Wv, wqkvh, wqkvl, 2048);
    split_gate<<<64, 256>>>(Wb, Wfd, Wsd, wgh, wgl);

    // fused QKV projection — launch #6, captured by ncu
    gemm_f16_512<<<dim3(NQKV / 128, TOK / 128), 512, SM512>>>(xh, wqkvh, wqkvl, qkv, NQKV);

    split_wt<<<gW, 256>>>(Wo, woh, wol, 0);
    gemm_f16_64<<<dim3(1, TOK / 128), 256, SM64>>>(xh, wgh, wgl, praw, 64);

    transform_k<<<TOK * Hsz / 8, 256>>>(qkv, praw, bfd, bsd,
                                        Wtf1, btf1, Wtf2, btf2,
                                        qh, kbh, vs, lgf, lgs, alpha);
    scan_k<<<BH, 512>>>(lgf, lgs, wf, ws, dinv);
    state_mma<<<dim3(BH, NCHUNK), 128, SMST>>>(kbh, vs, wf, ws, Mpart);
    reduceM_t<<<(2 * BH * 4096 + 255) / 256, 256>>>(Mpart, dinv, Mt);
    readout_mma<<<dim3(BH, Lsz / 128), 256>>>(qh, Mt, alpha, oh);

    gemm_f16_512<<<dim3(Dsz / 128, TOK / 128), 512, SM512>>>(oh, woh, wol, (float*)d_out, Dsz);
}